// round 8
// baseline (speedup 1.0000x reference)
#include <cuda_runtime.h>
#include <cuda_bf16.h>
#include <math.h>
#include <float.h>
#include <limits.h>
#include <stdint.h>

// Problem constants
#define Bb 2
#define Tt 2048
#define Dd 1024
#define Nn 16
#define Kk 8
#define Hh 128
#define Gg 2
#define Mrows (Bb*Tt)          // 4096

static constexpr float EPSf   = 1e-6f;
static constexpr float LOG_THETA = 13.815510557964274f;  // ln(1e6)
static constexpr float SCALEf = 0.08838834764831845f;    // 128^-0.5

// ---------------------------------------------------------------------------
// Scratch (allocation-free rule: __device__ globals)
// ---------------------------------------------------------------------------
__device__ int   g_pos[Mrows];

// bf16 split buffers
__device__ __nv_bfloat16 g_xhi[(size_t)Mrows * Dd];
__device__ __nv_bfloat16 g_xlo[(size_t)Mrows * Dd];
__device__ __nv_bfloat16 g_atthi[(size_t)Mrows * Nn * Hh];   // attn out [row][n*H]
__device__ __nv_bfloat16 g_attlo[(size_t)Mrows * Nn * Hh];
__device__ __nv_bfloat16 g_wqT_hi[(size_t)(Nn*Hh) * Dd];
__device__ __nv_bfloat16 g_wqT_lo[(size_t)(Nn*Hh) * Dd];
__device__ __nv_bfloat16 g_wkT_hi[(size_t)(Kk*Hh) * Dd];
__device__ __nv_bfloat16 g_wkT_lo[(size_t)(Kk*Hh) * Dd];
__device__ __nv_bfloat16 g_wvT_hi[(size_t)(Kk*Hh) * Dd];
__device__ __nv_bfloat16 g_wvT_lo[(size_t)(Kk*Hh) * Dd];
__device__ __nv_bfloat16 g_woT_hi[(size_t)Dd * (Nn*Hh)];
__device__ __nv_bfloat16 g_woT_lo[(size_t)Dd * (Nn*Hh)];

// head-major bf16 split q/k/v for attention: [b][head][t][h]
__device__ __nv_bfloat16 g_qhh[(size_t)Bb * Nn * Tt * Hh];
__device__ __nv_bfloat16 g_qhl[(size_t)Bb * Nn * Tt * Hh];
__device__ __nv_bfloat16 g_khh[(size_t)Bb * Kk * Tt * Hh];
__device__ __nv_bfloat16 g_khl[(size_t)Bb * Kk * Tt * Hh];
__device__ __nv_bfloat16 g_vhh[(size_t)Bb * Kk * Tt * Hh];
__device__ __nv_bfloat16 g_vhl[(size_t)Bb * Kk * Tt * Hh];

// ---------------------------------------------------------------------------
// PTX helpers (sm_103 baseline ISA: cp.async, ldmatrix, mma.sync)
// ---------------------------------------------------------------------------
__device__ __forceinline__ uint32_t smem_u32(const void* p) {
    uint32_t a;
    asm("{ .reg .u64 t; cvta.to.shared.u64 t, %1; cvt.u32.u64 %0, t; }"
        : "=r"(a) : "l"(p));
    return a;
}
#define SW128(off) ((off) ^ (((off) >> 3) & 0x70))

#define CP_ASYNC16(saddr, gaddr) \
    asm volatile("cp.async.cg.shared.global [%0], [%1], 16;" \
        :: "r"(saddr), "l"(gaddr) : "memory")
#define CP_COMMIT() asm volatile("cp.async.commit_group;" ::: "memory")
#define CP_WAIT(n)  asm volatile("cp.async.wait_group %0;" :: "n"(n) : "memory")

#define LDSM_X4(r, addr) \
    asm volatile("ldmatrix.sync.aligned.m8n8.x4.shared.b16 {%0,%1,%2,%3}, [%4];" \
        : "=r"((r)[0]), "=r"((r)[1]), "=r"((r)[2]), "=r"((r)[3]) : "r"(addr))
#define LDSM_X4_T(r, addr) \
    asm volatile("ldmatrix.sync.aligned.m8n8.x4.trans.shared.b16 {%0,%1,%2,%3}, [%4];" \
        : "=r"((r)[0]), "=r"((r)[1]), "=r"((r)[2]), "=r"((r)[3]) : "r"(addr))

#define MMA16816(d, a, b0r, b1r) \
    asm volatile("mma.sync.aligned.m16n8k16.row.col.f32.bf16.bf16.f32 " \
        "{%0,%1,%2,%3}, {%4,%5,%6,%7}, {%8,%9}, {%0,%1,%2,%3};" \
        : "+f"((d)[0]), "+f"((d)[1]), "+f"((d)[2]), "+f"((d)[3]) \
        : "r"((a)[0]), "r"((a)[1]), "r"((a)[2]), "r"((a)[3]), \
          "r"((b0r)), "r"((b1r)))

// Split fp32 pair into packed bf16 hi + packed bf16 residual.
__device__ __forceinline__ uint32_t split2(float x0, float x1, uint32_t& lopack) {
    __nv_bfloat16 h0 = __float2bfloat16(x0), h1 = __float2bfloat16(x1);
    float r0 = x0 - __bfloat162float(h0), r1 = x1 - __bfloat162float(h1);
    __nv_bfloat16 g0 = __float2bfloat16(r0), g1 = __float2bfloat16(r1);
    lopack = (uint32_t)__bfloat16_as_ushort(g0) | ((uint32_t)__bfloat16_as_ushort(g1) << 16);
    return (uint32_t)__bfloat16_as_ushort(h0) | ((uint32_t)__bfloat16_as_ushort(h1) << 16);
}

// ---------------------------------------------------------------------------
// positions_from_segment_ids
// ---------------------------------------------------------------------------
__global__ void pos_kernel(const int* __restrict__ seg) {
    int b = blockIdx.x;
    int tid = threadIdx.x;
    __shared__ int sv[256], si[256];
    int bv = INT_MIN, bi = INT_MAX;
    for (int t = tid; t < Tt; t += 256) {
        int v = seg[b * Tt + t];
        if (v > bv) { bv = v; bi = t; }
    }
    sv[tid] = bv; si[tid] = bi;
    __syncthreads();
    for (int o = 128; o; o >>= 1) {
        if (tid < o) {
            if (sv[tid + o] > sv[tid] ||
                (sv[tid + o] == sv[tid] && si[tid + o] < si[tid])) {
                sv[tid] = sv[tid + o]; si[tid] = si[tid + o];
            }
        }
        __syncthreads();
    }
    int off = si[0];
    for (int t = tid; t < Tt; t += 256) {
        int v = seg[b * Tt + t];
        g_pos[b * Tt + t] = (v != 0) ? (t - off) : (1 << 30);
    }
}

// ---------------------------------------------------------------------------
// fp32 -> (hi, lo) bf16 split, elementwise
// ---------------------------------------------------------------------------
__global__ __launch_bounds__(256)
void conv_split(const float* __restrict__ src, __nv_bfloat16* __restrict__ hi,
                __nv_bfloat16* __restrict__ lo, size_t n4) {
    size_t i = (size_t)blockIdx.x * blockDim.x + threadIdx.x;
    size_t stride = (size_t)gridDim.x * blockDim.x;
    for (; i < n4; i += stride) {
        float4 v = ((const float4*)src)[i];
        uint32_t l01, l23;
        uint32_t h01 = split2(v.x, v.y, l01);
        uint32_t h23 = split2(v.z, v.w, l23);
        ((uint2*)hi)[i] = make_uint2(h01, h23);
        ((uint2*)lo)[i] = make_uint2(l01, l23);
    }
}

// ---------------------------------------------------------------------------
// Transpose + split: w[Kd, Nc] fp32 -> wT_hi/lo[Nc, Kd] bf16
// ---------------------------------------------------------------------------
__global__ __launch_bounds__(256)
void conv_tsplit(const float* __restrict__ w, __nv_bfloat16* __restrict__ hi,
                 __nv_bfloat16* __restrict__ lo, int Kd, int Nc) {
    __shared__ float t[32][33];
    int n0 = blockIdx.x * 32, k0 = blockIdx.y * 32;
    int tx = threadIdx.x, ty = threadIdx.y;
    for (int i = ty; i < 32; i += 8)
        t[i][tx] = w[(size_t)(k0 + i) * Nc + n0 + tx];
    __syncthreads();
    for (int i = ty; i < 32; i += 8) {
        float v = t[tx][i];
        __nv_bfloat16 h = __float2bfloat16(v);
        __nv_bfloat16 l = __float2bfloat16(v - __bfloat162float(h));
        size_t o = (size_t)(n0 + i) * Kd + k0 + tx;
        hi[o] = h; lo[o] = l;
    }
}

// ---------------------------------------------------------------------------
// HMMA (mma.sync) bf16-split GEMM: C[M,Nc] = A[M,Kd] x Bt[Nc,Kd]^T
// 3-stage cp.async pipeline.
// mode 0: fp32 store to C
// mode 1: V split store (head-major bf16 hi/lo)
// mode 2: fused RMSNorm+RoPE+split (head-major bf16 hi/lo), per-head tiles
// ---------------------------------------------------------------------------
#define GSTAGE 65536
#define GEMM_SMEM (3 * GSTAGE)

__global__ __launch_bounds__(256)
void gemm_hmma(const __nv_bfloat16* __restrict__ Ahi, const __nv_bfloat16* __restrict__ Alo,
               const __nv_bfloat16* __restrict__ Bhi, const __nv_bfloat16* __restrict__ Blo,
               float* __restrict__ C,
               __nv_bfloat16* __restrict__ Oh, __nv_bfloat16* __restrict__ Ol,
               const float* __restrict__ scale, float post_scale, int heads,
               int mode, int Nc, int Kd) {
    extern __shared__ char smc[];
    const int tid  = threadIdx.x;
    const int lane = tid & 31;
    const int wid  = tid >> 5;
    const int warp_m = wid & 3;
    const int warp_n = wid >> 2;
    const int m0 = blockIdx.y * 128, n0 = blockIdx.x * 128;

    const int u = tid & 7;
    const int r = tid >> 3;

    const uint32_t sbase = smem_u32(smc);
    const int nchunk = Kd >> 6;

    float d[2][8][4];
#pragma unroll
    for (int mt = 0; mt < 2; mt++)
#pragma unroll
        for (int nt = 0; nt < 8; nt++)
#pragma unroll
            for (int j = 0; j < 4; j++) d[mt][nt][j] = 0.f;

#define ISSUE_CHUNK(c, s) do {                                               \
    const int k0e = (c) * 64;                                                \
    char* buf = smc + (s) * GSTAGE;                                          \
    _Pragma("unroll")                                                        \
    for (int i = 0; i < 4; i++) {                                            \
        int row = r + i * 32;                                                \
        uint32_t so = SW128(row * 128 + u * 16);                             \
        uint32_t sa = smem_u32(buf) + so;                                    \
        const __nv_bfloat16* pa_hi = Ahi + (size_t)(m0 + row) * Kd + k0e + u * 8; \
        const __nv_bfloat16* pa_lo = Alo + (size_t)(m0 + row) * Kd + k0e + u * 8; \
        const __nv_bfloat16* pb_hi = Bhi + (size_t)(n0 + row) * Kd + k0e + u * 8; \
        const __nv_bfloat16* pb_lo = Blo + (size_t)(n0 + row) * Kd + k0e + u * 8; \
        CP_ASYNC16(sa,         pa_hi);                                       \
        CP_ASYNC16(sa + 16384, pa_lo);                                       \
        CP_ASYNC16(sa + 32768, pb_hi);                                       \
        CP_ASYNC16(sa + 49152, pb_lo);                                       \
    }                                                                        \
} while (0)

    ISSUE_CHUNK(0, 0);
    CP_COMMIT();
    if (nchunk > 1) { ISSUE_CHUNK(1, 1); CP_COMMIT(); }

    int stage = 0;
    for (int c = 0; c < nchunk; c++) {
        if (c + 1 < nchunk) CP_WAIT(1); else CP_WAIT(0);
        __syncthreads();
        if (c + 2 < nchunk) {
            int ns = stage + 2; if (ns >= 3) ns -= 3;
            ISSUE_CHUNK(c + 2, ns);
            CP_COMMIT();
        }

        const uint32_t sb = sbase + stage * GSTAGE;
#pragma unroll
        for (int s = 0; s < 4; s++) {
            uint32_t aH[2][4], aL[2][4];
#pragma unroll
            for (int mt = 0; mt < 2; mt++) {
                int row  = warp_m * 32 + mt * 16 + (lane & 7) + ((lane >> 3) & 1) * 8;
                int unit = s * 2 + (lane >> 4);
                uint32_t addr = sb + SW128(row * 128 + unit * 16);
                LDSM_X4(aH[mt], addr);
                LDSM_X4(aL[mt], addr + 16384);
            }
            uint32_t bH[8][2], bL[8][2];
#pragma unroll
            for (int np = 0; np < 4; np++) {
                int row  = warp_n * 64 + np * 16 + ((lane >> 4) & 1) * 8 + (lane & 7);
                int unit = s * 2 + ((lane >> 3) & 1);
                uint32_t addr = sb + 32768 + SW128(row * 128 + unit * 16);
                uint32_t tmp[4];
                LDSM_X4(tmp, addr);
                bH[2*np][0] = tmp[0]; bH[2*np][1] = tmp[1];
                bH[2*np+1][0] = tmp[2]; bH[2*np+1][1] = tmp[3];
                LDSM_X4(tmp, addr + 16384);
                bL[2*np][0] = tmp[0]; bL[2*np][1] = tmp[1];
                bL[2*np+1][0] = tmp[2]; bL[2*np+1][1] = tmp[3];
            }
#pragma unroll
            for (int mt = 0; mt < 2; mt++)
#pragma unroll
                for (int nt = 0; nt < 8; nt++) {
                    MMA16816(d[mt][nt], aH[mt], bH[nt][0], bH[nt][1]);
                    MMA16816(d[mt][nt], aH[mt], bL[nt][0], bL[nt][1]);
                    MMA16816(d[mt][nt], aL[mt], bH[nt][0], bH[nt][1]);
                }
        }
        __syncthreads();
        if (++stage == 3) stage = 0;
    }

    if (mode == 0) {
#pragma unroll
        for (int mt = 0; mt < 2; mt++) {
#pragma unroll
            for (int nt = 0; nt < 8; nt++) {
                int row = m0 + warp_m * 32 + mt * 16 + (lane >> 2);
                int col = n0 + warp_n * 64 + nt * 8 + (lane & 3) * 2;
                *(float2*)&C[(size_t)row * Nc + col] =
                    make_float2(d[mt][nt][0], d[mt][nt][1]);
                *(float2*)&C[(size_t)(row + 8) * Nc + col] =
                    make_float2(d[mt][nt][2], d[mt][nt][3]);
            }
        }
    } else if (mode == 1) {
        // head-major split store for V: row = b*2048+t, col = kv*128+h
#pragma unroll
        for (int mt = 0; mt < 2; mt++) {
#pragma unroll
            for (int nt = 0; nt < 8; nt++) {
                int row = m0 + warp_m * 32 + mt * 16 + (lane >> 2);
                int col = n0 + warp_n * 64 + nt * 8 + (lane & 3) * 2;
                int bq = row >> 11, t = row & 2047;
                int kv = col >> 7, h = col & 127;
                size_t o0 = ((size_t)(bq * Kk + kv) * Tt + t) * Hh + h;
                size_t o1 = ((size_t)(bq * Kk + kv) * Tt + t + 8) * Hh + h;
                uint32_t lop;
                uint32_t hip = split2(d[mt][nt][0], d[mt][nt][1], lop);
                *(uint32_t*)(Oh + o0) = hip;
                *(uint32_t*)(Ol + o0) = lop;
                hip = split2(d[mt][nt][2], d[mt][nt][3], lop);
                *(uint32_t*)(Oh + o1) = hip;
                *(uint32_t*)(Ol + o1) = lop;
            }
        }
    } else {
        // mode 2: fused RMSNorm + RoPE + split, per-head tile (Nc tile == head)
        float* sStage = (float*)smc;                     // 128 x 133 fp32
        float* sSum   = (float*)(smc + 68096);           // [2][128]
        float* sRms   = (float*)(smc + 69120);           // [128]
        float* sScale = (float*)(smc + 69632);           // [128]

        // row sum-of-squares partials (64 cols per warp half)
        float ss[2][2];
#pragma unroll
        for (int mt = 0; mt < 2; mt++) {
            float a0 = 0.f, a1 = 0.f;
#pragma unroll
            for (int nt = 0; nt < 8; nt++) {
                a0 += d[mt][nt][0] * d[mt][nt][0] + d[mt][nt][1] * d[mt][nt][1];
                a1 += d[mt][nt][2] * d[mt][nt][2] + d[mt][nt][3] * d[mt][nt][3];
            }
            ss[mt][0] = a0; ss[mt][1] = a1;
        }
#pragma unroll
        for (int mt = 0; mt < 2; mt++)
#pragma unroll
            for (int rh = 0; rh < 2; rh++) {
                ss[mt][rh] += __shfl_xor_sync(0xffffffffu, ss[mt][rh], 1);
                ss[mt][rh] += __shfl_xor_sync(0xffffffffu, ss[mt][rh], 2);
            }
        if ((lane & 3) == 0) {
#pragma unroll
            for (int mt = 0; mt < 2; mt++)
#pragma unroll
                for (int rh = 0; rh < 2; rh++) {
                    int rl = warp_m * 32 + mt * 16 + rh * 8 + (lane >> 2);
                    sSum[warp_n * 128 + rl] = ss[mt][rh];
                }
        }
        if (tid < 128) sScale[tid] = scale[tid];
        // write raw values into staging
#pragma unroll
        for (int mt = 0; mt < 2; mt++) {
#pragma unroll
            for (int nt = 0; nt < 8; nt++) {
                int rl = warp_m * 32 + mt * 16 + (lane >> 2);
                int col = warp_n * 64 + nt * 8 + (lane & 3) * 2;
                sStage[rl * 133 + col]       = d[mt][nt][0];
                sStage[rl * 133 + col + 1]   = d[mt][nt][1];
                sStage[(rl + 8) * 133 + col]     = d[mt][nt][2];
                sStage[(rl + 8) * 133 + col + 1] = d[mt][nt][3];
            }
        }
        __syncthreads();
        if (tid < 128) {
            float total = sSum[tid] + sSum[128 + tid];
            sRms[tid] = rsqrtf(total * (1.0f / 128.0f) + EPSf);
        }
        __syncthreads();

        const int rl   = tid >> 1;          // local row 0..127
        const int half = tid & 1;           // h in [half*64, half*64+64)
        const int gr = m0 + rl;
        const int bq = gr >> 11, t = gr & 2047;
        const int head = n0 >> 7;
        const int pos = g_pos[gr];
        const float irms = sRms[rl];
        size_t obase = ((size_t)(bq * heads + head) * Tt + t) * Hh;
#pragma unroll 8
        for (int h0 = 0; h0 < 64; h0 += 2) {
            int h = half * 64 + h0;
            float o2[2];
#pragma unroll
            for (int j = 0; j < 2; j++) {
                int hh = h + j;
                int i = hh & 63;
                float inv_freq = __expf(-(float)i * (LOG_THETA / 64.0f));
                float ang = (float)pos * inv_freq;
                float sn = sinf(ang), cs = cosf(ang);
                float xa = sStage[rl * 133 + hh] * irms * sScale[hh];
                float xb = sStage[rl * 133 + (hh ^ 64)] * irms * sScale[hh ^ 64];
                float o = (hh < 64) ? (xa * cs - xb * sn) : (xa * cs + xb * sn);
                o2[j] = o * post_scale;
            }
            uint32_t lop;
            uint32_t hip = split2(o2[0], o2[1], lop);
            *(uint32_t*)(Oh + obase + h) = hip;
            *(uint32_t*)(Ol + obase + h) = lop;
        }
    }
#undef ISSUE_CHUNK
}

// ---------------------------------------------------------------------------
// HMMA flash attention, GQA-paired (one CTA per kv-head, both q-heads).
// ---------------------------------------------------------------------------
#define AT_ST0  65536
#define AT_POS  196608
#define AT_SEG  204800
#define AT_META 212992
#define ATT_SMEM (212992 + 512)

__global__ __launch_bounds__(256)
void attn_hmma(const int* __restrict__ seg_g) {
    extern __shared__ char sm[];
    const uint32_t sb = smem_u32(sm);
    int* sPos  = (int*)(sm + AT_POS);
    int* sSeg  = (int*)(sm + AT_SEG);
    int* sKmin = (int*)(sm + AT_META);
    int* sTiles = sKmin + 32;
    int* sCtl   = sTiles + 32;

    const int tid = threadIdx.x, lane = tid & 31, warp = tid >> 5;
    const int qbase = blockIdx.x * 64;
    const int kvh = blockIdx.y, b = blockIdx.z;
    const int hsel = warp >> 2;
    const int mwarp = warp & 3;
    const int n = kvh * 2 + hsel;

    for (int i = tid; i < 2048; i += 256) {
        sPos[i] = g_pos[b * Tt + i];
        sSeg[i] = seg_g[b * Tt + i];
    }
    for (int i = tid; i < 2048; i += 256) {
        int hh = i >> 10;
        int j = i & 1023;
        int r = j >> 4, u = j & 15;
        uint32_t off = hh * 32768 + ((u >> 3) << 13) + SW128(r * 128 + (u & 7) * 16);
        const char* qh = (const char*)(g_qhh + ((size_t)(b * Nn + kvh * 2 + hh) * Tt + qbase) * Hh);
        const char* ql = (const char*)(g_qhl + ((size_t)(b * Nn + kvh * 2 + hh) * Tt + qbase) * Hh);
        *(uint4*)(sm + off)         = *(const uint4*)(qh + r * 256 + u * 16);
        *(uint4*)(sm + 16384 + off) = *(const uint4*)(ql + r * 256 + u * 16);
    }
    __syncthreads();

    {
#pragma unroll
        for (int j = 0; j < 4; j++) {
            int tt = warp * 4 + j;
            int mn = min(sPos[tt * 64 + lane], sPos[tt * 64 + 32 + lane]);
#pragma unroll
            for (int o = 16; o; o >>= 1) mn = min(mn, __shfl_xor_sync(0xffffffffu, mn, o));
            if (lane == 0) sKmin[tt] = mn;
        }
        if (warp == 0) {
            int v = max(sPos[qbase + lane], sPos[qbase + 32 + lane]);
#pragma unroll
            for (int o = 16; o; o >>= 1) v = max(v, __shfl_xor_sync(0xffffffffu, v, o));
            if (lane == 0) sCtl[0] = v;
        }
    }
    __syncthreads();
    if (tid == 0) {
        int qmax = sCtl[0], na = 0;
        for (int tt = 0; tt < 32; tt++)
            if (sKmin[tt] <= qmax) sTiles[na++] = tt;
        sCtl[1] = na;
    }
    __syncthreads();
    const int nactive = sCtl[1];

    const char* kh = (const char*)(g_khh + ((size_t)(b * Kk + kvh) * Tt) * Hh);
    const char* kl = (const char*)(g_khl + ((size_t)(b * Kk + kvh) * Tt) * Hh);
    const char* vh = (const char*)(g_vhh + ((size_t)(b * Kk + kvh) * Tt) * Hh);
    const char* vl = (const char*)(g_vhl + ((size_t)(b * Kk + kvh) * Tt) * Hh);

#define AT_ISSUE(tt, st) do {                                                \
    const int sbase_ = (tt) * 64;                                            \
    uint32_t stb = sb + AT_ST0 + (st) * 65536;                               \
    for (int i = tid; i < 1024; i += 256) {                                  \
        int r = i >> 4, u = i & 15;                                          \
        uint32_t off = ((u >> 3) << 13) + SW128(r * 128 + (u & 7) * 16);     \
        size_t go = (size_t)(sbase_ + r) * 256 + u * 16;                     \
        CP_ASYNC16(stb + off,         kh + go);                              \
        CP_ASYNC16(stb + 16384 + off, kl + go);                              \
        CP_ASYNC16(stb + 32768 + off, vh + go);                              \
        CP_ASYNC16(stb + 49152 + off, vl + go);                              \
    }                                                                        \
} while (0)

    const int r_lo = mwarp * 16 + (lane >> 2);
    const int qp0 = sPos[qbase + r_lo];
    const int qp1 = sPos[qbase + r_lo + 8];
    const int qs0 = sSeg[qbase + r_lo];
    const int qs1 = sSeg[qbase + r_lo + 8];

    float d_o[16][4];
#pragma unroll
    for (int nt = 0; nt < 16; nt++)
#pragma unroll
        for (int j = 0; j < 4; j++) d_o[nt][j] = 0.f;
    float m0 = -1e30f, m1 = -1e30f, l0 = 0.f, l1 = 0.f;

    const int qrow_l = mwarp * 16 + (lane & 7) + ((lane >> 3) & 1) * 8;
    const int krow_l = ((lane >> 4) & 1) * 8 + (lane & 7);
    const int vrow_l = (((lane >> 3) & 1) << 3) + (lane & 7);
    const int qh_sel = (lane >> 4) << 3;
    const int kh_sel = ((lane >> 3) & 1) << 3;
    const int vh_sel = (lane >> 4) << 3;
    const uint32_t qpanel = sb + hsel * 32768;

    if (nactive > 0) { AT_ISSUE(sTiles[0], 0); CP_COMMIT(); }

    for (int j = 0; j < nactive; j++) {
        const int tt = sTiles[j];
        const int sbase = tt * 64;
        if (j + 1 < nactive) { AT_ISSUE(sTiles[j + 1], (j + 1) & 1); CP_COMMIT(); CP_WAIT(1); }
        else                 { CP_WAIT(0); }
        __syncthreads();

        const uint32_t stb = sb + AT_ST0 + (j & 1) * 65536;

        float ds[8][4];
#pragma unroll
        for (int nt = 0; nt < 8; nt++)
#pragma unroll
            for (int jj = 0; jj < 4; jj++) ds[nt][jj] = 0.f;

#pragma unroll
        for (int ks = 0; ks < 8; ks++) {
            int hq = ks * 16 + qh_sel;
            uint32_t qoff = ((hq >> 6) << 13) + SW128(qrow_l * 128 + ((hq & 63) << 1));
            uint32_t aH[4], aL[4];
            LDSM_X4(aH, qpanel + qoff);
            LDSM_X4(aL, qpanel + 16384 + qoff);
            int hk = ks * 16 + kh_sel;
            uint32_t kpan = ((hk >> 6) << 13);
            uint32_t kcol = (hk & 63) << 1;
#pragma unroll
            for (int np = 0; np < 4; np++) {
                uint32_t addr = stb + kpan + SW128((np * 16 + krow_l) * 128 + kcol);
                uint32_t tH[4], tL[4];
                LDSM_X4(tH, addr);
                LDSM_X4(tL, addr + 16384);
                MMA16816(ds[2*np],   aH, tH[0], tH[1]);
                MMA16816(ds[2*np],   aH, tL[0], tL[1]);
                MMA16816(ds[2*np],   aL, tH[0], tH[1]);
                MMA16816(ds[2*np+1], aH, tH[2], tH[3]);
                MMA16816(ds[2*np+1], aH, tL[2], tL[3]);
                MMA16816(ds[2*np+1], aL, tH[2], tH[3]);
            }
        }

#pragma unroll
        for (int nt = 0; nt < 8; nt++) {
            int c = sbase + nt * 8 + (lane & 3) * 2;
            int kp0 = sPos[c], kp1 = sPos[c + 1];
            int ks0 = sSeg[c], ks1 = sSeg[c + 1];
            if (!(kp0 <= qp0 && ks0 == qs0)) ds[nt][0] = -1e30f;
            if (!(kp1 <= qp0 && ks1 == qs0)) ds[nt][1] = -1e30f;
            if (!(kp0 <= qp1 && ks0 == qs1)) ds[nt][2] = -1e30f;
            if (!(kp1 <= qp1 && ks1 == qs1)) ds[nt][3] = -1e30f;
        }

        float tm0 = -1e30f, tm1 = -1e30f;
#pragma unroll
        for (int nt = 0; nt < 8; nt++) {
            tm0 = fmaxf(tm0, fmaxf(ds[nt][0], ds[nt][1]));
            tm1 = fmaxf(tm1, fmaxf(ds[nt][2], ds[nt][3]));
        }
        tm0 = fmaxf(tm0, __shfl_xor_sync(0xffffffffu, tm0, 1));
        tm0 = fmaxf(tm0, __shfl_xor_sync(0xffffffffu, tm0, 2));
        tm1 = fmaxf(tm1, __shfl_xor_sync(0xffffffffu, tm1, 1));
        tm1 = fmaxf(tm1, __shfl_xor_sync(0xffffffffu, tm1, 2));
        float nm0 = fmaxf(m0, tm0), nm1 = fmaxf(m1, tm1);
        float a0 = __expf(m0 - nm0), a1 = __expf(m1 - nm1);
        float gg0 = (nm0 > -0.9e30f) ? 1.f : 0.f;
        float gg1 = (nm1 > -0.9e30f) ? 1.f : 0.f;
        float s0 = 0.f, s1 = 0.f;
#pragma unroll
        for (int nt = 0; nt < 8; nt++) {
            ds[nt][0] = gg0 * __expf(ds[nt][0] - nm0);
            ds[nt][1] = gg0 * __expf(ds[nt][1] - nm0);
            ds[nt][2] = gg1 * __expf(ds[nt][2] - nm1);
            ds[nt][3] = gg1 * __expf(ds[nt][3] - nm1);
            s0 += ds[nt][0] + ds[nt][1];
            s1 += ds[nt][2] + ds[nt][3];
        }
        s0 += __shfl_xor_sync(0xffffffffu, s0, 1);
        s0 += __shfl_xor_sync(0xffffffffu, s0, 2);
        s1 += __shfl_xor_sync(0xffffffffu, s1, 1);
        s1 += __shfl_xor_sync(0xffffffffu, s1, 2);
        l0 = l0 * a0 + s0; m0 = nm0;
        l1 = l1 * a1 + s1; m1 = nm1;
#pragma unroll
        for (int nt = 0; nt < 16; nt++) {
            d_o[nt][0] *= a0; d_o[nt][1] *= a0;
            d_o[nt][2] *= a1; d_o[nt][3] *= a1;
        }

        uint32_t Ph[4][4], Pl[4][4];
#pragma unroll
        for (int kb = 0; kb < 4; kb++) {
            Ph[kb][0] = split2(ds[2*kb][0],   ds[2*kb][1],   Pl[kb][0]);
            Ph[kb][1] = split2(ds[2*kb][2],   ds[2*kb][3],   Pl[kb][1]);
            Ph[kb][2] = split2(ds[2*kb+1][0], ds[2*kb+1][1], Pl[kb][2]);
            Ph[kb][3] = split2(ds[2*kb+1][2], ds[2*kb+1][3], Pl[kb][3]);
        }

#pragma unroll
        for (int ntp = 0; ntp < 8; ntp++) {
            int hv = ntp * 16 + vh_sel;
            uint32_t vpan = ((hv >> 6) << 13);
            uint32_t vcol = (hv & 63) << 1;
#pragma unroll
            for (int kb = 0; kb < 4; kb++) {
                uint32_t addr = stb + 32768 + vpan + SW128((kb * 16 + vrow_l) * 128 + vcol);
                uint32_t tH[4], tL[4];
                LDSM_X4_T(tH, addr);
                LDSM_X4_T(tL, addr + 16384);
                MMA16816(d_o[2*ntp],   Ph[kb], tH[0], tH[1]);
                MMA16816(d_o[2*ntp],   Pl[kb], tH[0], tH[1]);
                MMA16816(d_o[2*ntp],   Ph[kb], tL[0], tL[1]);
                MMA16816(d_o[2*ntp+1], Ph[kb], tH[2], tH[3]);
                MMA16816(d_o[2*ntp+1], Pl[kb], tH[2], tH[3]);
                MMA16816(d_o[2*ntp+1], Ph[kb], tL[2], tL[3]);
            }
        }
        __syncthreads();
    }
#undef AT_ISSUE

    float il0 = (l0 > 0.f) ? (1.f / l0) : 0.f;
    float il1 = (l1 > 0.f) ? (1.f / l1) : 0.f;
    size_t base0 = ((size_t)(b * Tt + qbase + r_lo))     * 2048 + n * 128;
    size_t base1 = ((size_t)(b * Tt + qbase + r_lo + 8)) * 2048 + n * 128;
#pragma unroll
    for (int nt = 0; nt < 16; nt++) {
        int h = nt * 8 + (lane & 3) * 2;
        uint32_t lop;
        uint32_t hip = split2(d_o[nt][0] * il0, d_o[nt][1] * il0, lop);
        *(uint32_t*)(g_atthi + base0 + h) = hip;
        *(uint32_t*)(g_attlo + base0 + h) = lop;
        hip = split2(d_o[nt][2] * il1, d_o[nt][3] * il1, lop);
        *(uint32_t*)(g_atthi + base1 + h) = hip;
        *(uint32_t*)(g_attlo + base1 + h) = lop;
    }
}

// ---------------------------------------------------------------------------
extern "C" void kernel_launch(void* const* d_in, const int* in_sizes, int n_in,
                              void* d_out, int out_size) {
    const float* x       = (const float*)d_in[0];
    const int*   seg     = (const int*)  d_in[1];
    const float* wq      = (const float*)d_in[2];
    const float* wk      = (const float*)d_in[3];
    const float* wv      = (const float*)d_in[4];
    const float* wo      = (const float*)d_in[5];
    const float* q_scale = (const float*)d_in[6];
    const float* k_scale = (const float*)d_in[7];
    float* out = (float*)d_out;

    __nv_bfloat16 *xhi, *xlo, *ahi, *alo;
    __nv_bfloat16 *wqh, *wql, *wkh, *wkl, *wvh, *wvl, *woh, *wol;
    __nv_bfloat16 *qhh, *qhl, *khh, *khl, *vhh, *vhl;
    cudaGetSymbolAddress((void**)&xhi, g_xhi);
    cudaGetSymbolAddress((void**)&xlo, g_xlo);
    cudaGetSymbolAddress((void**)&ahi, g_atthi);
    cudaGetSymbolAddress((void**)&alo, g_attlo);
    cudaGetSymbolAddress((void**)&wqh, g_wqT_hi);
    cudaGetSymbolAddress((void**)&wql, g_wqT_lo);
    cudaGetSymbolAddress((void**)&wkh, g_wkT_hi);
    cudaGetSymbolAddress((void**)&wkl, g_wkT_lo);
    cudaGetSymbolAddress((void**)&wvh, g_wvT_hi);
    cudaGetSymbolAddress((void**)&wvl, g_wvT_lo);
    cudaGetSymbolAddress((void**)&woh, g_woT_hi);
    cudaGetSymbolAddress((void**)&wol, g_woT_lo);
    cudaGetSymbolAddress((void**)&qhh, g_qhh);
    cudaGetSymbolAddress((void**)&qhl, g_qhl);
    cudaGetSymbolAddress((void**)&khh, g_khh);
    cudaGetSymbolAddress((void**)&khl, g_khl);
    cudaGetSymbolAddress((void**)&vhh, g_vhh);
    cudaGetSymbolAddress((void**)&vhl, g_vhl);

    cudaFuncSetAttribute(gemm_hmma, cudaFuncAttributeMaxDynamicSharedMemorySize,
                         GEMM_SMEM);
    cudaFuncSetAttribute(attn_hmma, cudaFuncAttributeMaxDynamicSharedMemorySize,
                         ATT_SMEM);

    pos_kernel<<<Bb, 256>>>(seg);

    // split conversions
    conv_split<<<1024, 256>>>(x, xhi, xlo, (size_t)Mrows * Dd / 4);
    conv_tsplit<<<dim3(2048 / 32, 1024 / 32), dim3(32, 8)>>>(wq, wqh, wql, 1024, 2048);
    conv_tsplit<<<dim3(1024 / 32, 1024 / 32), dim3(32, 8)>>>(wk, wkh, wkl, 1024, 1024);
    conv_tsplit<<<dim3(1024 / 32, 1024 / 32), dim3(32, 8)>>>(wv, wvh, wvl, 1024, 1024);
    conv_tsplit<<<dim3(1024 / 32, 2048 / 32), dim3(32, 8)>>>(wo, woh, wol, 2048, 1024);

    // Q projection: fused RMSNorm + RoPE + split (pre-scaled by SCALE)
    gemm_hmma<<<dim3(2048 / 128, Mrows / 128), 256, GEMM_SMEM>>>(
        xhi, xlo, wqh, wql, (float*)0, qhh, qhl, q_scale, SCALEf, Nn, 2, 2048, 1024);
    // K projection: fused RMSNorm + RoPE + split
    gemm_hmma<<<dim3(1024 / 128, Mrows / 128), 256, GEMM_SMEM>>>(
        xhi, xlo, wkh, wkl, (float*)0, khh, khl, k_scale, 1.0f, Kk, 2, 1024, 1024);
    // V projection: head-major split store
    gemm_hmma<<<dim3(1024 / 128, Mrows / 128), 256, GEMM_SMEM>>>(
        xhi, xlo, wvh, wvl, (float*)0, vhh, vhl, (const float*)0, 1.0f, Kk, 1, 1024, 1024);

    // HMMA flash attention (GQA-paired, cp.async pipelined)
    attn_hmma<<<dim3(Tt / 64, Kk, Bb), 256, ATT_SMEM>>>(seg);

    // output projection (plain fp32 store to d_out)
    gemm_hmma<<<dim3(1024 / 128, Mrows / 128), 256, GEMM_SMEM>>>(
        ahi, alo, woh, wol, out, (__nv_bfloat16*)0, (__nv_bfloat16*)0,
        (const float*)0, 1.0f, 0, 0, 1024, 2048);
}

// round 9
// speedup vs baseline: 1.0134x; 1.0134x over previous
#include <cuda_runtime.h>
#include <cuda_bf16.h>
#include <math.h>
#include <float.h>
#include <limits.h>
#include <stdint.h>

// Problem constants
#define Bb 2
#define Tt 2048
#define Dd 1024
#define Nn 16
#define Kk 8
#define Hh 128
#define Gg 2
#define Mrows (Bb*Tt)          // 4096

static constexpr float EPSf   = 1e-6f;
static constexpr float LOG_THETA = 13.815510557964274f;  // ln(1e6)
static constexpr float SCALEf = 0.08838834764831845f;    // 128^-0.5

// ---------------------------------------------------------------------------
// Scratch (allocation-free rule: __device__ globals)
// ---------------------------------------------------------------------------
__device__ int    g_pos[Mrows];
__device__ float2 g_rope[(size_t)Mrows * 64];            // (sin, cos) per (row, i)

// bf16 split buffers
__device__ __nv_bfloat16 g_xhi[(size_t)Mrows * Dd];
__device__ __nv_bfloat16 g_xlo[(size_t)Mrows * Dd];
__device__ __nv_bfloat16 g_atthi[(size_t)Mrows * Nn * Hh];   // attn out [row][n*H]
__device__ __nv_bfloat16 g_attlo[(size_t)Mrows * Nn * Hh];
__device__ __nv_bfloat16 g_wqT_hi[(size_t)(Nn*Hh) * Dd];
__device__ __nv_bfloat16 g_wqT_lo[(size_t)(Nn*Hh) * Dd];
__device__ __nv_bfloat16 g_wkT_hi[(size_t)(Kk*Hh) * Dd];
__device__ __nv_bfloat16 g_wkT_lo[(size_t)(Kk*Hh) * Dd];
__device__ __nv_bfloat16 g_wvT_hi[(size_t)(Kk*Hh) * Dd];
__device__ __nv_bfloat16 g_wvT_lo[(size_t)(Kk*Hh) * Dd];
__device__ __nv_bfloat16 g_woT_hi[(size_t)Dd * (Nn*Hh)];
__device__ __nv_bfloat16 g_woT_lo[(size_t)Dd * (Nn*Hh)];

// head-major bf16 split q/k/v for attention: [b][head][t][h]
__device__ __nv_bfloat16 g_qhh[(size_t)Bb * Nn * Tt * Hh];
__device__ __nv_bfloat16 g_qhl[(size_t)Bb * Nn * Tt * Hh];
__device__ __nv_bfloat16 g_khh[(size_t)Bb * Kk * Tt * Hh];
__device__ __nv_bfloat16 g_khl[(size_t)Bb * Kk * Tt * Hh];
__device__ __nv_bfloat16 g_vhh[(size_t)Bb * Kk * Tt * Hh];
__device__ __nv_bfloat16 g_vhl[(size_t)Bb * Kk * Tt * Hh];

// ---------------------------------------------------------------------------
// PTX helpers (sm_103 baseline ISA: cp.async, ldmatrix, mma.sync)
// ---------------------------------------------------------------------------
__device__ __forceinline__ uint32_t smem_u32(const void* p) {
    uint32_t a;
    asm("{ .reg .u64 t; cvta.to.shared.u64 t, %1; cvt.u32.u64 %0, t; }"
        : "=r"(a) : "l"(p));
    return a;
}
#define SW128(off) ((off) ^ (((off) >> 3) & 0x70))

#define CP_ASYNC16(saddr, gaddr) \
    asm volatile("cp.async.cg.shared.global [%0], [%1], 16;" \
        :: "r"(saddr), "l"(gaddr) : "memory")
#define CP_COMMIT() asm volatile("cp.async.commit_group;" ::: "memory")
#define CP_WAIT(n)  asm volatile("cp.async.wait_group %0;" :: "n"(n) : "memory")

#define LDSM_X4(r, addr) \
    asm volatile("ldmatrix.sync.aligned.m8n8.x4.shared.b16 {%0,%1,%2,%3}, [%4];" \
        : "=r"((r)[0]), "=r"((r)[1]), "=r"((r)[2]), "=r"((r)[3]) : "r"(addr))
#define LDSM_X4_T(r, addr) \
    asm volatile("ldmatrix.sync.aligned.m8n8.x4.trans.shared.b16 {%0,%1,%2,%3}, [%4];" \
        : "=r"((r)[0]), "=r"((r)[1]), "=r"((r)[2]), "=r"((r)[3]) : "r"(addr))

#define MMA16816(d, a, b0r, b1r) \
    asm volatile("mma.sync.aligned.m16n8k16.row.col.f32.bf16.bf16.f32 " \
        "{%0,%1,%2,%3}, {%4,%5,%6,%7}, {%8,%9}, {%0,%1,%2,%3};" \
        : "+f"((d)[0]), "+f"((d)[1]), "+f"((d)[2]), "+f"((d)[3]) \
        : "r"((a)[0]), "r"((a)[1]), "r"((a)[2]), "r"((a)[3]), \
          "r"((b0r)), "r"((b1r)))

// Split fp32 pair into packed bf16 hi + packed bf16 residual.
__device__ __forceinline__ uint32_t split2(float x0, float x1, uint32_t& lopack) {
    __nv_bfloat16 h0 = __float2bfloat16(x0), h1 = __float2bfloat16(x1);
    float r0 = x0 - __bfloat162float(h0), r1 = x1 - __bfloat162float(h1);
    __nv_bfloat16 g0 = __float2bfloat16(r0), g1 = __float2bfloat16(r1);
    lopack = (uint32_t)__bfloat16_as_ushort(g0) | ((uint32_t)__bfloat16_as_ushort(g1) << 16);
    return (uint32_t)__bfloat16_as_ushort(h0) | ((uint32_t)__bfloat16_as_ushort(h1) << 16);
}

// ---------------------------------------------------------------------------
// positions_from_segment_ids
// ---------------------------------------------------------------------------
__global__ void pos_kernel(const int* __restrict__ seg) {
    int b = blockIdx.x;
    int tid = threadIdx.x;
    __shared__ int sv[256], si[256];
    int bv = INT_MIN, bi = INT_MAX;
    for (int t = tid; t < Tt; t += 256) {
        int v = seg[b * Tt + t];
        if (v > bv) { bv = v; bi = t; }
    }
    sv[tid] = bv; si[tid] = bi;
    __syncthreads();
    for (int o = 128; o; o >>= 1) {
        if (tid < o) {
            if (sv[tid + o] > sv[tid] ||
                (sv[tid + o] == sv[tid] && si[tid + o] < si[tid])) {
                sv[tid] = sv[tid + o]; si[tid] = si[tid + o];
            }
        }
        __syncthreads();
    }
    int off = si[0];
    for (int t = tid; t < Tt; t += 256) {
        int v = seg[b * Tt + t];
        g_pos[b * Tt + t] = (v != 0) ? (t - off) : (1 << 30);
    }
}

// ---------------------------------------------------------------------------
// RoPE sin/cos table: g_rope[row*64 + i]
// ---------------------------------------------------------------------------
__global__ __launch_bounds__(256)
void rope_kernel() {
    int idx = blockIdx.x * 256 + threadIdx.x;     // Mrows*64
    int gr = idx >> 6, i = idx & 63;
    int pos = g_pos[gr];
    float inv_freq = __expf(-(float)i * (LOG_THETA / 64.0f));
    float ang = (float)pos * inv_freq;
    g_rope[idx] = make_float2(sinf(ang), cosf(ang));
}

// ---------------------------------------------------------------------------
// fp32 -> (hi, lo) bf16 split, elementwise
// ---------------------------------------------------------------------------
__global__ __launch_bounds__(256)
void conv_split(const float* __restrict__ src, __nv_bfloat16* __restrict__ hi,
                __nv_bfloat16* __restrict__ lo, size_t n4) {
    size_t i = (size_t)blockIdx.x * blockDim.x + threadIdx.x;
    size_t stride = (size_t)gridDim.x * blockDim.x;
    for (; i < n4; i += stride) {
        float4 v = ((const float4*)src)[i];
        uint32_t l01, l23;
        uint32_t h01 = split2(v.x, v.y, l01);
        uint32_t h23 = split2(v.z, v.w, l23);
        ((uint2*)hi)[i] = make_uint2(h01, h23);
        ((uint2*)lo)[i] = make_uint2(l01, l23);
    }
}

// ---------------------------------------------------------------------------
// Transpose + split: w[Kd, Nc] fp32 -> wT_hi/lo[Nc, Kd] bf16
// ---------------------------------------------------------------------------
__global__ __launch_bounds__(256)
void conv_tsplit(const float* __restrict__ w, __nv_bfloat16* __restrict__ hi,
                 __nv_bfloat16* __restrict__ lo, int Kd, int Nc) {
    __shared__ float t[32][33];
    int n0 = blockIdx.x * 32, k0 = blockIdx.y * 32;
    int tx = threadIdx.x, ty = threadIdx.y;
    for (int i = ty; i < 32; i += 8)
        t[i][tx] = w[(size_t)(k0 + i) * Nc + n0 + tx];
    __syncthreads();
    for (int i = ty; i < 32; i += 8) {
        float v = t[tx][i];
        __nv_bfloat16 h = __float2bfloat16(v);
        __nv_bfloat16 l = __float2bfloat16(v - __bfloat162float(h));
        size_t o = (size_t)(n0 + i) * Kd + k0 + tx;
        hi[o] = h; lo[o] = l;
    }
}

// ---------------------------------------------------------------------------
// HMMA (mma.sync) bf16-split GEMM: C[M,Nc] = A[M,Kd] x Bt[Nc,Kd]^T
// 2-stage cp.async pipeline (R7 structure).
// mode 0: fp32 store to C
// mode 1: V split store (head-major bf16 hi/lo)
// mode 2: fused RMSNorm+RoPE(table)+split (head-major bf16 hi/lo)
// ---------------------------------------------------------------------------
#define GSTAGE 65536
#define GEMM_SMEM (2 * GSTAGE)

__global__ __launch_bounds__(256)
void gemm_hmma(const __nv_bfloat16* __restrict__ Ahi, const __nv_bfloat16* __restrict__ Alo,
               const __nv_bfloat16* __restrict__ Bhi, const __nv_bfloat16* __restrict__ Blo,
               float* __restrict__ C,
               __nv_bfloat16* __restrict__ Oh, __nv_bfloat16* __restrict__ Ol,
               const float* __restrict__ scale, float post_scale, int heads,
               int mode, int Nc, int Kd) {
    extern __shared__ char smc[];
    const int tid  = threadIdx.x;
    const int lane = tid & 31;
    const int wid  = tid >> 5;
    const int warp_m = wid & 3;
    const int warp_n = wid >> 2;
    const int m0 = blockIdx.y * 128, n0 = blockIdx.x * 128;

    const int u = tid & 7;
    const int r = tid >> 3;

    const uint32_t sbase = smem_u32(smc);
    const int nchunk = Kd >> 6;

    float d[2][8][4];
#pragma unroll
    for (int mt = 0; mt < 2; mt++)
#pragma unroll
        for (int nt = 0; nt < 8; nt++)
#pragma unroll
            for (int j = 0; j < 4; j++) d[mt][nt][j] = 0.f;

#define ISSUE_CHUNK(c, s) do {                                               \
    const int k0e = (c) * 64;                                                \
    char* buf = smc + (s) * GSTAGE;                                          \
    _Pragma("unroll")                                                        \
    for (int i = 0; i < 4; i++) {                                            \
        int row = r + i * 32;                                                \
        uint32_t so = SW128(row * 128 + u * 16);                             \
        uint32_t sa = smem_u32(buf) + so;                                    \
        const __nv_bfloat16* pa_hi = Ahi + (size_t)(m0 + row) * Kd + k0e + u * 8; \
        const __nv_bfloat16* pa_lo = Alo + (size_t)(m0 + row) * Kd + k0e + u * 8; \
        const __nv_bfloat16* pb_hi = Bhi + (size_t)(n0 + row) * Kd + k0e + u * 8; \
        const __nv_bfloat16* pb_lo = Blo + (size_t)(n0 + row) * Kd + k0e + u * 8; \
        CP_ASYNC16(sa,         pa_hi);                                       \
        CP_ASYNC16(sa + 16384, pa_lo);                                       \
        CP_ASYNC16(sa + 32768, pb_hi);                                       \
        CP_ASYNC16(sa + 49152, pb_lo);                                       \
    }                                                                        \
} while (0)

    ISSUE_CHUNK(0, 0);
    CP_COMMIT();

    for (int c = 0; c < nchunk; c++) {
        if (c + 1 < nchunk) { ISSUE_CHUNK(c + 1, (c + 1) & 1); CP_COMMIT(); CP_WAIT(1); }
        else                { CP_WAIT(0); }
        __syncthreads();

        const uint32_t sb = sbase + (c & 1) * GSTAGE;
#pragma unroll
        for (int s = 0; s < 4; s++) {
            uint32_t aH[2][4], aL[2][4];
#pragma unroll
            for (int mt = 0; mt < 2; mt++) {
                int row  = warp_m * 32 + mt * 16 + (lane & 7) + ((lane >> 3) & 1) * 8;
                int unit = s * 2 + (lane >> 4);
                uint32_t addr = sb + SW128(row * 128 + unit * 16);
                LDSM_X4(aH[mt], addr);
                LDSM_X4(aL[mt], addr + 16384);
            }
            uint32_t bH[8][2], bL[8][2];
#pragma unroll
            for (int np = 0; np < 4; np++) {
                int row  = warp_n * 64 + np * 16 + ((lane >> 4) & 1) * 8 + (lane & 7);
                int unit = s * 2 + ((lane >> 3) & 1);
                uint32_t addr = sb + 32768 + SW128(row * 128 + unit * 16);
                uint32_t tmp[4];
                LDSM_X4(tmp, addr);
                bH[2*np][0] = tmp[0]; bH[2*np][1] = tmp[1];
                bH[2*np+1][0] = tmp[2]; bH[2*np+1][1] = tmp[3];
                LDSM_X4(tmp, addr + 16384);
                bL[2*np][0] = tmp[0]; bL[2*np][1] = tmp[1];
                bL[2*np+1][0] = tmp[2]; bL[2*np+1][1] = tmp[3];
            }
#pragma unroll
            for (int mt = 0; mt < 2; mt++)
#pragma unroll
                for (int nt = 0; nt < 8; nt++) {
                    MMA16816(d[mt][nt], aH[mt], bH[nt][0], bH[nt][1]);
                    MMA16816(d[mt][nt], aH[mt], bL[nt][0], bL[nt][1]);
                    MMA16816(d[mt][nt], aL[mt], bH[nt][0], bH[nt][1]);
                }
        }
        __syncthreads();
    }

    if (mode == 0) {
#pragma unroll
        for (int mt = 0; mt < 2; mt++) {
#pragma unroll
            for (int nt = 0; nt < 8; nt++) {
                int row = m0 + warp_m * 32 + mt * 16 + (lane >> 2);
                int col = n0 + warp_n * 64 + nt * 8 + (lane & 3) * 2;
                *(float2*)&C[(size_t)row * Nc + col] =
                    make_float2(d[mt][nt][0], d[mt][nt][1]);
                *(float2*)&C[(size_t)(row + 8) * Nc + col] =
                    make_float2(d[mt][nt][2], d[mt][nt][3]);
            }
        }
    } else if (mode == 1) {
        // head-major split store for V: row = b*2048+t, col = kv*128+h
#pragma unroll
        for (int mt = 0; mt < 2; mt++) {
#pragma unroll
            for (int nt = 0; nt < 8; nt++) {
                int row = m0 + warp_m * 32 + mt * 16 + (lane >> 2);
                int col = n0 + warp_n * 64 + nt * 8 + (lane & 3) * 2;
                int bq = row >> 11, t = row & 2047;
                int kv = col >> 7, h = col & 127;
                size_t o0 = ((size_t)(bq * Kk + kv) * Tt + t) * Hh + h;
                size_t o1 = ((size_t)(bq * Kk + kv) * Tt + t + 8) * Hh + h;
                uint32_t lop;
                uint32_t hip = split2(d[mt][nt][0], d[mt][nt][1], lop);
                *(uint32_t*)(Oh + o0) = hip;
                *(uint32_t*)(Ol + o0) = lop;
                hip = split2(d[mt][nt][2], d[mt][nt][3], lop);
                *(uint32_t*)(Oh + o1) = hip;
                *(uint32_t*)(Ol + o1) = lop;
            }
        }
    } else {
        // mode 2: fused RMSNorm + RoPE(table) + split, per-head tile
        float* sStage = (float*)smc;                     // 128 x 133 fp32
        float* sSum   = (float*)(smc + 68096);           // [2][128]
        float* sRms   = (float*)(smc + 69120);           // [128]
        float* sScale = (float*)(smc + 69632);           // [128]

        float ss[2][2];
#pragma unroll
        for (int mt = 0; mt < 2; mt++) {
            float a0 = 0.f, a1 = 0.f;
#pragma unroll
            for (int nt = 0; nt < 8; nt++) {
                a0 += d[mt][nt][0] * d[mt][nt][0] + d[mt][nt][1] * d[mt][nt][1];
                a1 += d[mt][nt][2] * d[mt][nt][2] + d[mt][nt][3] * d[mt][nt][3];
            }
            ss[mt][0] = a0; ss[mt][1] = a1;
        }
#pragma unroll
        for (int mt = 0; mt < 2; mt++)
#pragma unroll
            for (int rh = 0; rh < 2; rh++) {
                ss[mt][rh] += __shfl_xor_sync(0xffffffffu, ss[mt][rh], 1);
                ss[mt][rh] += __shfl_xor_sync(0xffffffffu, ss[mt][rh], 2);
            }
        if ((lane & 3) == 0) {
#pragma unroll
            for (int mt = 0; mt < 2; mt++)
#pragma unroll
                for (int rh = 0; rh < 2; rh++) {
                    int rl = warp_m * 32 + mt * 16 + rh * 8 + (lane >> 2);
                    sSum[warp_n * 128 + rl] = ss[mt][rh];
                }
        }
        if (tid < 128) sScale[tid] = scale[tid];
#pragma unroll
        for (int mt = 0; mt < 2; mt++) {
#pragma unroll
            for (int nt = 0; nt < 8; nt++) {
                int rl = warp_m * 32 + mt * 16 + (lane >> 2);
                int col = warp_n * 64 + nt * 8 + (lane & 3) * 2;
                sStage[rl * 133 + col]       = d[mt][nt][0];
                sStage[rl * 133 + col + 1]   = d[mt][nt][1];
                sStage[(rl + 8) * 133 + col]     = d[mt][nt][2];
                sStage[(rl + 8) * 133 + col + 1] = d[mt][nt][3];
            }
        }
        __syncthreads();
        if (tid < 128) {
            float total = sSum[tid] + sSum[128 + tid];
            sRms[tid] = rsqrtf(total * (1.0f / 128.0f) + EPSf);
        }
        __syncthreads();

        const int rl   = tid >> 1;          // local row 0..127
        const int half = tid & 1;           // h in [half*64, half*64+64)
        const int gr = m0 + rl;
        const int bq = gr >> 11, t = gr & 2047;
        const int head = n0 >> 7;
        const float irms = sRms[rl];
        const float sgn = half ? 1.f : -1.f;
        const float2* rope = g_rope + (size_t)gr * 64;
        size_t obase = ((size_t)(bq * heads + head) * Tt + t) * Hh;
#pragma unroll 8
        for (int h0 = 0; h0 < 64; h0 += 2) {
            int h = half * 64 + h0;
            float o2[2];
#pragma unroll
            for (int j = 0; j < 2; j++) {
                int hh = h + j;
                float2 sc = rope[h0 + j];
                float xa = sStage[rl * 133 + hh] * irms * sScale[hh];
                float xb = sStage[rl * 133 + (hh ^ 64)] * irms * sScale[hh ^ 64];
                o2[j] = (xa * sc.y + sgn * xb * sc.x) * post_scale;
            }
            uint32_t lop;
            uint32_t hip = split2(o2[0], o2[1], lop);
            *(uint32_t*)(Oh + obase + h) = hip;
            *(uint32_t*)(Ol + obase + h) = lop;
        }
    }
#undef ISSUE_CHUNK
}

// ---------------------------------------------------------------------------
// HMMA flash attention, GQA-paired (one CTA per kv-head, both q-heads).
// ---------------------------------------------------------------------------
#define AT_ST0  65536
#define AT_POS  196608
#define AT_SEG  204800
#define AT_META 212992
#define ATT_SMEM (212992 + 512)

__global__ __launch_bounds__(256)
void attn_hmma(const int* __restrict__ seg_g) {
    extern __shared__ char sm[];
    const uint32_t sb = smem_u32(sm);
    int* sPos  = (int*)(sm + AT_POS);
    int* sSeg  = (int*)(sm + AT_SEG);
    int* sKmin = (int*)(sm + AT_META);
    int* sTiles = sKmin + 32;
    int* sCtl   = sTiles + 32;

    const int tid = threadIdx.x, lane = tid & 31, warp = tid >> 5;
    const int qbase = blockIdx.x * 64;
    const int kvh = blockIdx.y, b = blockIdx.z;
    const int hsel = warp >> 2;
    const int mwarp = warp & 3;
    const int n = kvh * 2 + hsel;

    for (int i = tid; i < 2048; i += 256) {
        sPos[i] = g_pos[b * Tt + i];
        sSeg[i] = seg_g[b * Tt + i];
    }
    for (int i = tid; i < 2048; i += 256) {
        int hh = i >> 10;
        int j = i & 1023;
        int r = j >> 4, u = j & 15;
        uint32_t off = hh * 32768 + ((u >> 3) << 13) + SW128(r * 128 + (u & 7) * 16);
        const char* qh = (const char*)(g_qhh + ((size_t)(b * Nn + kvh * 2 + hh) * Tt + qbase) * Hh);
        const char* ql = (const char*)(g_qhl + ((size_t)(b * Nn + kvh * 2 + hh) * Tt + qbase) * Hh);
        *(uint4*)(sm + off)         = *(const uint4*)(qh + r * 256 + u * 16);
        *(uint4*)(sm + 16384 + off) = *(const uint4*)(ql + r * 256 + u * 16);
    }
    __syncthreads();

    {
#pragma unroll
        for (int j = 0; j < 4; j++) {
            int tt = warp * 4 + j;
            int mn = min(sPos[tt * 64 + lane], sPos[tt * 64 + 32 + lane]);
#pragma unroll
            for (int o = 16; o; o >>= 1) mn = min(mn, __shfl_xor_sync(0xffffffffu, mn, o));
            if (lane == 0) sKmin[tt] = mn;
        }
        if (warp == 0) {
            int v = max(sPos[qbase + lane], sPos[qbase + 32 + lane]);
#pragma unroll
            for (int o = 16; o; o >>= 1) v = max(v, __shfl_xor_sync(0xffffffffu, v, o));
            if (lane == 0) sCtl[0] = v;
        }
    }
    __syncthreads();
    if (tid == 0) {
        int qmax = sCtl[0], na = 0;
        for (int tt = 0; tt < 32; tt++)
            if (sKmin[tt] <= qmax) sTiles[na++] = tt;
        sCtl[1] = na;
    }
    __syncthreads();
    const int nactive = sCtl[1];

    const char* kh = (const char*)(g_khh + ((size_t)(b * Kk + kvh) * Tt) * Hh);
    const char* kl = (const char*)(g_khl + ((size_t)(b * Kk + kvh) * Tt) * Hh);
    const char* vh = (const char*)(g_vhh + ((size_t)(b * Kk + kvh) * Tt) * Hh);
    const char* vl = (const char*)(g_vhl + ((size_t)(b * Kk + kvh) * Tt) * Hh);

#define AT_ISSUE(tt, st) do {                                                \
    const int sbase_ = (tt) * 64;                                            \
    uint32_t stb = sb + AT_ST0 + (st) * 65536;                               \
    for (int i = tid; i < 1024; i += 256) {                                  \
        int r = i >> 4, u = i & 15;                                          \
        uint32_t off = ((u >> 3) << 13) + SW128(r * 128 + (u & 7) * 16);     \
        size_t go = (size_t)(sbase_ + r) * 256 + u * 16;                     \
        CP_ASYNC16(stb + off,         kh + go);                              \
        CP_ASYNC16(stb + 16384 + off, kl + go);                              \
        CP_ASYNC16(stb + 32768 + off, vh + go);                              \
        CP_ASYNC16(stb + 49152 + off, vl + go);                              \
    }                                                                        \
} while (0)

    const int r_lo = mwarp * 16 + (lane >> 2);
    const int qp0 = sPos[qbase + r_lo];
    const int qp1 = sPos[qbase + r_lo + 8];
    const int qs0 = sSeg[qbase + r_lo];
    const int qs1 = sSeg[qbase + r_lo + 8];

    float d_o[16][4];
#pragma unroll
    for (int nt = 0; nt < 16; nt++)
#pragma unroll
        for (int j = 0; j < 4; j++) d_o[nt][j] = 0.f;
    float m0 = -1e30f, m1 = -1e30f, l0 = 0.f, l1 = 0.f;

    const int qrow_l = mwarp * 16 + (lane & 7) + ((lane >> 3) & 1) * 8;
    const int krow_l = ((lane >> 4) & 1) * 8 + (lane & 7);
    const int vrow_l = (((lane >> 3) & 1) << 3) + (lane & 7);
    const int qh_sel = (lane >> 4) << 3;
    const int kh_sel = ((lane >> 3) & 1) << 3;
    const int vh_sel = (lane >> 4) << 3;
    const uint32_t qpanel = sb + hsel * 32768;

    if (nactive > 0) { AT_ISSUE(sTiles[0], 0); CP_COMMIT(); }

    for (int j = 0; j < nactive; j++) {
        const int tt = sTiles[j];
        const int sbase = tt * 64;
        if (j + 1 < nactive) { AT_ISSUE(sTiles[j + 1], (j + 1) & 1); CP_COMMIT(); CP_WAIT(1); }
        else                 { CP_WAIT(0); }
        __syncthreads();

        const uint32_t stb = sb + AT_ST0 + (j & 1) * 65536;

        float ds[8][4];
#pragma unroll
        for (int nt = 0; nt < 8; nt++)
#pragma unroll
            for (int jj = 0; jj < 4; jj++) ds[nt][jj] = 0.f;

#pragma unroll
        for (int ks = 0; ks < 8; ks++) {
            int hq = ks * 16 + qh_sel;
            uint32_t qoff = ((hq >> 6) << 13) + SW128(qrow_l * 128 + ((hq & 63) << 1));
            uint32_t aH[4], aL[4];
            LDSM_X4(aH, qpanel + qoff);
            LDSM_X4(aL, qpanel + 16384 + qoff);
            int hk = ks * 16 + kh_sel;
            uint32_t kpan = ((hk >> 6) << 13);
            uint32_t kcol = (hk & 63) << 1;
#pragma unroll
            for (int np = 0; np < 4; np++) {
                uint32_t addr = stb + kpan + SW128((np * 16 + krow_l) * 128 + kcol);
                uint32_t tH[4], tL[4];
                LDSM_X4(tH, addr);
                LDSM_X4(tL, addr + 16384);
                MMA16816(ds[2*np],   aH, tH[0], tH[1]);
                MMA16816(ds[2*np],   aH, tL[0], tL[1]);
                MMA16816(ds[2*np],   aL, tH[0], tH[1]);
                MMA16816(ds[2*np+1], aH, tH[2], tH[3]);
                MMA16816(ds[2*np+1], aH, tL[2], tL[3]);
                MMA16816(ds[2*np+1], aL, tH[2], tH[3]);
            }
        }

#pragma unroll
        for (int nt = 0; nt < 8; nt++) {
            int c = sbase + nt * 8 + (lane & 3) * 2;
            int kp0 = sPos[c], kp1 = sPos[c + 1];
            int ks0 = sSeg[c], ks1 = sSeg[c + 1];
            if (!(kp0 <= qp0 && ks0 == qs0)) ds[nt][0] = -1e30f;
            if (!(kp1 <= qp0 && ks1 == qs0)) ds[nt][1] = -1e30f;
            if (!(kp0 <= qp1 && ks0 == qs1)) ds[nt][2] = -1e30f;
            if (!(kp1 <= qp1 && ks1 == qs1)) ds[nt][3] = -1e30f;
        }

        float tm0 = -1e30f, tm1 = -1e30f;
#pragma unroll
        for (int nt = 0; nt < 8; nt++) {
            tm0 = fmaxf(tm0, fmaxf(ds[nt][0], ds[nt][1]));
            tm1 = fmaxf(tm1, fmaxf(ds[nt][2], ds[nt][3]));
        }
        tm0 = fmaxf(tm0, __shfl_xor_sync(0xffffffffu, tm0, 1));
        tm0 = fmaxf(tm0, __shfl_xor_sync(0xffffffffu, tm0, 2));
        tm1 = fmaxf(tm1, __shfl_xor_sync(0xffffffffu, tm1, 1));
        tm1 = fmaxf(tm1, __shfl_xor_sync(0xffffffffu, tm1, 2));
        float nm0 = fmaxf(m0, tm0), nm1 = fmaxf(m1, tm1);
        float a0 = __expf(m0 - nm0), a1 = __expf(m1 - nm1);
        float gg0 = (nm0 > -0.9e30f) ? 1.f : 0.f;
        float gg1 = (nm1 > -0.9e30f) ? 1.f : 0.f;
        float s0 = 0.f, s1 = 0.f;
#pragma unroll
        for (int nt = 0; nt < 8; nt++) {
            ds[nt][0] = gg0 * __expf(ds[nt][0] - nm0);
            ds[nt][1] = gg0 * __expf(ds[nt][1] - nm0);
            ds[nt][2] = gg1 * __expf(ds[nt][2] - nm1);
            ds[nt][3] = gg1 * __expf(ds[nt][3] - nm1);
            s0 += ds[nt][0] + ds[nt][1];
            s1 += ds[nt][2] + ds[nt][3];
        }
        s0 += __shfl_xor_sync(0xffffffffu, s0, 1);
        s0 += __shfl_xor_sync(0xffffffffu, s0, 2);
        s1 += __shfl_xor_sync(0xffffffffu, s1, 1);
        s1 += __shfl_xor_sync(0xffffffffu, s1, 2);
        l0 = l0 * a0 + s0; m0 = nm0;
        l1 = l1 * a1 + s1; m1 = nm1;
#pragma unroll
        for (int nt = 0; nt < 16; nt++) {
            d_o[nt][0] *= a0; d_o[nt][1] *= a0;
            d_o[nt][2] *= a1; d_o[nt][3] *= a1;
        }

        uint32_t Ph[4][4], Pl[4][4];
#pragma unroll
        for (int kb = 0; kb < 4; kb++) {
            Ph[kb][0] = split2(ds[2*kb][0],   ds[2*kb][1],   Pl[kb][0]);
            Ph[kb][1] = split2(ds[2*kb][2],   ds[2*kb][3],   Pl[kb][1]);
            Ph[kb][2] = split2(ds[2*kb+1][0], ds[2*kb+1][1], Pl[kb][2]);
            Ph[kb][3] = split2(ds[2*kb+1][2], ds[2*kb+1][3], Pl[kb][3]);
        }

#pragma unroll
        for (int ntp = 0; ntp < 8; ntp++) {
            int hv = ntp * 16 + vh_sel;
            uint32_t vpan = ((hv >> 6) << 13);
            uint32_t vcol = (hv & 63) << 1;
#pragma unroll
            for (int kb = 0; kb < 4; kb++) {
                uint32_t addr = stb + 32768 + vpan + SW128((kb * 16 + vrow_l) * 128 + vcol);
                uint32_t tH[4], tL[4];
                LDSM_X4_T(tH, addr);
                LDSM_X4_T(tL, addr + 16384);
                MMA16816(d_o[2*ntp],   Ph[kb], tH[0], tH[1]);
                MMA16816(d_o[2*ntp],   Pl[kb], tH[0], tH[1]);
                MMA16816(d_o[2*ntp],   Ph[kb], tL[0], tL[1]);
                MMA16816(d_o[2*ntp+1], Ph[kb], tH[2], tH[3]);
                MMA16816(d_o[2*ntp+1], Pl[kb], tH[2], tH[3]);
                MMA16816(d_o[2*ntp+1], Ph[kb], tL[2], tL[3]);
            }
        }
        __syncthreads();
    }
#undef AT_ISSUE

    float il0 = (l0 > 0.f) ? (1.f / l0) : 0.f;
    float il1 = (l1 > 0.f) ? (1.f / l1) : 0.f;
    size_t base0 = ((size_t)(b * Tt + qbase + r_lo))     * 2048 + n * 128;
    size_t base1 = ((size_t)(b * Tt + qbase + r_lo + 8)) * 2048 + n * 128;
#pragma unroll
    for (int nt = 0; nt < 16; nt++) {
        int h = nt * 8 + (lane & 3) * 2;
        uint32_t lop;
        uint32_t hip = split2(d_o[nt][0] * il0, d_o[nt][1] * il0, lop);
        *(uint32_t*)(g_atthi + base0 + h) = hip;
        *(uint32_t*)(g_attlo + base0 + h) = lop;
        hip = split2(d_o[nt][2] * il1, d_o[nt][3] * il1, lop);
        *(uint32_t*)(g_atthi + base1 + h) = hip;
        *(uint32_t*)(g_attlo + base1 + h) = lop;
    }
}

// ---------------------------------------------------------------------------
extern "C" void kernel_launch(void* const* d_in, const int* in_sizes, int n_in,
                              void* d_out, int out_size) {
    const float* x       = (const float*)d_in[0];
    const int*   seg     = (const int*)  d_in[1];
    const float* wq      = (const float*)d_in[2];
    const float* wk      = (const float*)d_in[3];
    const float* wv      = (const float*)d_in[4];
    const float* wo      = (const float*)d_in[5];
    const float* q_scale = (const float*)d_in[6];
    const float* k_scale = (const float*)d_in[7];
    float* out = (float*)d_out;

    __nv_bfloat16 *xhi, *xlo, *ahi, *alo;
    __nv_bfloat16 *wqh, *wql, *wkh, *wkl, *wvh, *wvl, *woh, *wol;
    __nv_bfloat16 *qhh, *qhl, *khh, *khl, *vhh, *vhl;
    cudaGetSymbolAddress((void**)&xhi, g_xhi);
    cudaGetSymbolAddress((void**)&xlo, g_xlo);
    cudaGetSymbolAddress((void**)&ahi, g_atthi);
    cudaGetSymbolAddress((void**)&alo, g_attlo);
    cudaGetSymbolAddress((void**)&wqh, g_wqT_hi);
    cudaGetSymbolAddress((void**)&wql, g_wqT_lo);
    cudaGetSymbolAddress((void**)&wkh, g_wkT_hi);
    cudaGetSymbolAddress((void**)&wkl, g_wkT_lo);
    cudaGetSymbolAddress((void**)&wvh, g_wvT_hi);
    cudaGetSymbolAddress((void**)&wvl, g_wvT_lo);
    cudaGetSymbolAddress((void**)&woh, g_woT_hi);
    cudaGetSymbolAddress((void**)&wol, g_woT_lo);
    cudaGetSymbolAddress((void**)&qhh, g_qhh);
    cudaGetSymbolAddress((void**)&qhl, g_qhl);
    cudaGetSymbolAddress((void**)&khh, g_khh);
    cudaGetSymbolAddress((void**)&khl, g_khl);
    cudaGetSymbolAddress((void**)&vhh, g_vhh);
    cudaGetSymbolAddress((void**)&vhl, g_vhl);

    cudaFuncSetAttribute(gemm_hmma, cudaFuncAttributeMaxDynamicSharedMemorySize,
                         GEMM_SMEM);
    cudaFuncSetAttribute(attn_hmma, cudaFuncAttributeMaxDynamicSharedMemorySize,
                         ATT_SMEM);

    pos_kernel<<<Bb, 256>>>(seg);
    rope_kernel<<<Mrows * 64 / 256, 256>>>();

    // split conversions
    conv_split<<<1024, 256>>>(x, xhi, xlo, (size_t)Mrows * Dd / 4);
    conv_tsplit<<<dim3(2048 / 32, 1024 / 32), dim3(32, 8)>>>(wq, wqh, wql, 1024, 2048);
    conv_tsplit<<<dim3(1024 / 32, 1024 / 32), dim3(32, 8)>>>(wk, wkh, wkl, 1024, 1024);
    conv_tsplit<<<dim3(1024 / 32, 1024 / 32), dim3(32, 8)>>>(wv, wvh, wvl, 1024, 1024);
    conv_tsplit<<<dim3(1024 / 32, 2048 / 32), dim3(32, 8)>>>(wo, woh, wol, 2048, 1024);

    // Q projection: fused RMSNorm + RoPE + split (pre-scaled by SCALE)
    gemm_hmma<<<dim3(2048 / 128, Mrows / 128), 256, GEMM_SMEM>>>(
        xhi, xlo, wqh, wql, (float*)0, qhh, qhl, q_scale, SCALEf, Nn, 2, 2048, 1024);
    // K projection: fused RMSNorm + RoPE + split
    gemm_hmma<<<dim3(1024 / 128, Mrows / 128), 256, GEMM_SMEM>>>(
        xhi, xlo, wkh, wkl, (float*)0, khh, khl, k_scale, 1.0f, Kk, 2, 1024, 1024);
    // V projection: head-major split store
    gemm_hmma<<<dim3(1024 / 128, Mrows / 128), 256, GEMM_SMEM>>>(
        xhi, xlo, wvh, wvl, (float*)0, vhh, vhl, (const float*)0, 1.0f, Kk, 1, 1024, 1024);

    // HMMA flash attention (GQA-paired, cp.async pipelined)
    attn_hmma<<<dim3(Tt / 64, Kk, Bb), 256, ATT_SMEM>>>(seg);

    // output projection (plain fp32 store to d_out)
    gemm_hmma<<<dim3(1024 / 128, Mrows / 128), 256, GEMM_SMEM>>>(
        ahi, alo, woh, wol, out, (__nv_bfloat16*)0, (__nv_bfloat16*)0,
        (const float*)0, 1.0f, 0, 0, 1024, 2048);
}

// round 10
// speedup vs baseline: 1.1012x; 1.0866x over previous
#include <cuda_runtime.h>
#include <cuda_bf16.h>
#include <math.h>
#include <float.h>
#include <limits.h>
#include <stdint.h>

// Problem constants
#define Bb 2
#define Tt 2048
#define Dd 1024
#define Nn 16
#define Kk 8
#define Hh 128
#define Gg 2
#define Mrows (Bb*Tt)          // 4096

static constexpr float EPSf   = 1e-6f;
static constexpr float LOG_THETA = 13.815510557964274f;  // ln(1e6)
static constexpr float SCALEf = 0.08838834764831845f;    // 128^-0.5

// ---------------------------------------------------------------------------
// Scratch (allocation-free rule: __device__ globals)
// ---------------------------------------------------------------------------
__device__ int    g_pos[Mrows];
__device__ float2 g_rope[(size_t)Mrows * 64];            // (sin, cos) per (row, i)
__device__ float  g_qkv[(size_t)Mrows * 4096];           // fp32 q|k cols 0..3071 (v bypasses)

// bf16 split buffers
__device__ __nv_bfloat16 g_xhi[(size_t)Mrows * Dd];
__device__ __nv_bfloat16 g_xlo[(size_t)Mrows * Dd];
__device__ __nv_bfloat16 g_atthi[(size_t)Mrows * Nn * Hh];   // attn out [row][n*H]
__device__ __nv_bfloat16 g_attlo[(size_t)Mrows * Nn * Hh];
__device__ __nv_bfloat16 g_wqkvT_hi[(size_t)4096 * Dd];      // [wq|wk|wv]^T rows
__device__ __nv_bfloat16 g_wqkvT_lo[(size_t)4096 * Dd];
__device__ __nv_bfloat16 g_woT_hi[(size_t)Dd * (Nn*Hh)];
__device__ __nv_bfloat16 g_woT_lo[(size_t)Dd * (Nn*Hh)];

// head-major bf16 split q/k/v for attention: [b][head][t][h]
__device__ __nv_bfloat16 g_qhh[(size_t)Bb * Nn * Tt * Hh];
__device__ __nv_bfloat16 g_qhl[(size_t)Bb * Nn * Tt * Hh];
__device__ __nv_bfloat16 g_khh[(size_t)Bb * Kk * Tt * Hh];
__device__ __nv_bfloat16 g_khl[(size_t)Bb * Kk * Tt * Hh];
__device__ __nv_bfloat16 g_vhh[(size_t)Bb * Kk * Tt * Hh];
__device__ __nv_bfloat16 g_vhl[(size_t)Bb * Kk * Tt * Hh];

// ---------------------------------------------------------------------------
// PTX helpers (sm_103 baseline ISA: cp.async, ldmatrix, mma.sync)
// ---------------------------------------------------------------------------
__device__ __forceinline__ uint32_t smem_u32(const void* p) {
    uint32_t a;
    asm("{ .reg .u64 t; cvta.to.shared.u64 t, %1; cvt.u32.u64 %0, t; }"
        : "=r"(a) : "l"(p));
    return a;
}
#define SW128(off) ((off) ^ (((off) >> 3) & 0x70))

#define CP_ASYNC16(saddr, gaddr) \
    asm volatile("cp.async.cg.shared.global [%0], [%1], 16;" \
        :: "r"(saddr), "l"(gaddr) : "memory")
#define CP_COMMIT() asm volatile("cp.async.commit_group;" ::: "memory")
#define CP_WAIT(n)  asm volatile("cp.async.wait_group %0;" :: "n"(n) : "memory")

#define LDSM_X4(r, addr) \
    asm volatile("ldmatrix.sync.aligned.m8n8.x4.shared.b16 {%0,%1,%2,%3}, [%4];" \
        : "=r"((r)[0]), "=r"((r)[1]), "=r"((r)[2]), "=r"((r)[3]) : "r"(addr))
#define LDSM_X4_T(r, addr) \
    asm volatile("ldmatrix.sync.aligned.m8n8.x4.trans.shared.b16 {%0,%1,%2,%3}, [%4];" \
        : "=r"((r)[0]), "=r"((r)[1]), "=r"((r)[2]), "=r"((r)[3]) : "r"(addr))

#define MMA16816(d, a, b0r, b1r) \
    asm volatile("mma.sync.aligned.m16n8k16.row.col.f32.bf16.bf16.f32 " \
        "{%0,%1,%2,%3}, {%4,%5,%6,%7}, {%8,%9}, {%0,%1,%2,%3};" \
        : "+f"((d)[0]), "+f"((d)[1]), "+f"((d)[2]), "+f"((d)[3]) \
        : "r"((a)[0]), "r"((a)[1]), "r"((a)[2]), "r"((a)[3]), \
          "r"((b0r)), "r"((b1r)))

// Split fp32 pair into packed bf16 hi + packed bf16 residual.
__device__ __forceinline__ uint32_t split2(float x0, float x1, uint32_t& lopack) {
    __nv_bfloat16 h0 = __float2bfloat16(x0), h1 = __float2bfloat16(x1);
    float r0 = x0 - __bfloat162float(h0), r1 = x1 - __bfloat162float(h1);
    __nv_bfloat16 g0 = __float2bfloat16(r0), g1 = __float2bfloat16(r1);
    lopack = (uint32_t)__bfloat16_as_ushort(g0) | ((uint32_t)__bfloat16_as_ushort(g1) << 16);
    return (uint32_t)__bfloat16_as_ushort(h0) | ((uint32_t)__bfloat16_as_ushort(h1) << 16);
}

// ---------------------------------------------------------------------------
// positions_from_segment_ids
// ---------------------------------------------------------------------------
__global__ void pos_kernel(const int* __restrict__ seg) {
    int b = blockIdx.x;
    int tid = threadIdx.x;
    __shared__ int sv[256], si[256];
    int bv = INT_MIN, bi = INT_MAX;
    for (int t = tid; t < Tt; t += 256) {
        int v = seg[b * Tt + t];
        if (v > bv) { bv = v; bi = t; }
    }
    sv[tid] = bv; si[tid] = bi;
    __syncthreads();
    for (int o = 128; o; o >>= 1) {
        if (tid < o) {
            if (sv[tid + o] > sv[tid] ||
                (sv[tid + o] == sv[tid] && si[tid + o] < si[tid])) {
                sv[tid] = sv[tid + o]; si[tid] = si[tid + o];
            }
        }
        __syncthreads();
    }
    int off = si[0];
    for (int t = tid; t < Tt; t += 256) {
        int v = seg[b * Tt + t];
        g_pos[b * Tt + t] = (v != 0) ? (t - off) : (1 << 30);
    }
}

// ---------------------------------------------------------------------------
// RoPE sin/cos table: g_rope[row*64 + i]
// ---------------------------------------------------------------------------
__global__ __launch_bounds__(256)
void rope_kernel() {
    int idx = blockIdx.x * 256 + threadIdx.x;     // Mrows*64
    int gr = idx >> 6, i = idx & 63;
    int pos = g_pos[gr];
    float inv_freq = __expf(-(float)i * (LOG_THETA / 64.0f));
    float ang = (float)pos * inv_freq;
    g_rope[idx] = make_float2(sinf(ang), cosf(ang));
}

// ---------------------------------------------------------------------------
// fp32 -> (hi, lo) bf16 split, elementwise
// ---------------------------------------------------------------------------
__global__ __launch_bounds__(256)
void conv_split(const float* __restrict__ src, __nv_bfloat16* __restrict__ hi,
                __nv_bfloat16* __restrict__ lo, size_t n4) {
    size_t i = (size_t)blockIdx.x * blockDim.x + threadIdx.x;
    size_t stride = (size_t)gridDim.x * blockDim.x;
    for (; i < n4; i += stride) {
        float4 v = ((const float4*)src)[i];
        uint32_t l01, l23;
        uint32_t h01 = split2(v.x, v.y, l01);
        uint32_t h23 = split2(v.z, v.w, l23);
        ((uint2*)hi)[i] = make_uint2(h01, h23);
        ((uint2*)lo)[i] = make_uint2(l01, l23);
    }
}

// ---------------------------------------------------------------------------
// Transpose + split: w[Kd, Nc] fp32 -> wT_hi/lo[Nc, Kd] bf16
// ---------------------------------------------------------------------------
__global__ __launch_bounds__(256)
void conv_tsplit(const float* __restrict__ w, __nv_bfloat16* __restrict__ hi,
                 __nv_bfloat16* __restrict__ lo, int Kd, int Nc) {
    __shared__ float t[32][33];
    int n0 = blockIdx.x * 32, k0 = blockIdx.y * 32;
    int tx = threadIdx.x, ty = threadIdx.y;
    for (int i = ty; i < 32; i += 8)
        t[i][tx] = w[(size_t)(k0 + i) * Nc + n0 + tx];
    __syncthreads();
    for (int i = ty; i < 32; i += 8) {
        float v = t[tx][i];
        __nv_bfloat16 h = __float2bfloat16(v);
        __nv_bfloat16 l = __float2bfloat16(v - __bfloat162float(h));
        size_t o = (size_t)(n0 + i) * Kd + k0 + tx;
        hi[o] = h; lo[o] = l;
    }
}

// ---------------------------------------------------------------------------
// HMMA (mma.sync) bf16-split GEMM: C[M,Nc] = A[M,Kd] x Bt[Nc,Kd]^T
// 2-stage cp.async pipeline (R7 structure).
// mode 0: fp32 store to C
// mode 3: combined QKV: col tiles 0..23 -> fp32 store (q|k), 24..31 -> V split
// ---------------------------------------------------------------------------
#define GSTAGE 65536
#define GEMM_SMEM (2 * GSTAGE)

__global__ __launch_bounds__(256)
void gemm_hmma(const __nv_bfloat16* __restrict__ Ahi, const __nv_bfloat16* __restrict__ Alo,
               const __nv_bfloat16* __restrict__ Bhi, const __nv_bfloat16* __restrict__ Blo,
               float* __restrict__ C,
               __nv_bfloat16* __restrict__ Oh, __nv_bfloat16* __restrict__ Ol,
               int mode, int Nc, int Kd) {
    extern __shared__ char smc[];
    const int tid  = threadIdx.x;
    const int lane = tid & 31;
    const int wid  = tid >> 5;
    const int warp_m = wid & 3;
    const int warp_n = wid >> 2;
    const int m0 = blockIdx.y * 128, n0 = blockIdx.x * 128;

    const int u = tid & 7;
    const int r = tid >> 3;

    const uint32_t sbase = smem_u32(smc);
    const int nchunk = Kd >> 6;

    float d[2][8][4];
#pragma unroll
    for (int mt = 0; mt < 2; mt++)
#pragma unroll
        for (int nt = 0; nt < 8; nt++)
#pragma unroll
            for (int j = 0; j < 4; j++) d[mt][nt][j] = 0.f;

#define ISSUE_CHUNK(c, s) do {                                               \
    const int k0e = (c) * 64;                                                \
    char* buf = smc + (s) * GSTAGE;                                          \
    _Pragma("unroll")                                                        \
    for (int i = 0; i < 4; i++) {                                            \
        int row = r + i * 32;                                                \
        uint32_t so = SW128(row * 128 + u * 16);                             \
        uint32_t sa = smem_u32(buf) + so;                                    \
        const __nv_bfloat16* pa_hi = Ahi + (size_t)(m0 + row) * Kd + k0e + u * 8; \
        const __nv_bfloat16* pa_lo = Alo + (size_t)(m0 + row) * Kd + k0e + u * 8; \
        const __nv_bfloat16* pb_hi = Bhi + (size_t)(n0 + row) * Kd + k0e + u * 8; \
        const __nv_bfloat16* pb_lo = Blo + (size_t)(n0 + row) * Kd + k0e + u * 8; \
        CP_ASYNC16(sa,         pa_hi);                                       \
        CP_ASYNC16(sa + 16384, pa_lo);                                       \
        CP_ASYNC16(sa + 32768, pb_hi);                                       \
        CP_ASYNC16(sa + 49152, pb_lo);                                       \
    }                                                                        \
} while (0)

    ISSUE_CHUNK(0, 0);
    CP_COMMIT();

    for (int c = 0; c < nchunk; c++) {
        if (c + 1 < nchunk) { ISSUE_CHUNK(c + 1, (c + 1) & 1); CP_COMMIT(); CP_WAIT(1); }
        else                { CP_WAIT(0); }
        __syncthreads();

        const uint32_t sb = sbase + (c & 1) * GSTAGE;
#pragma unroll
        for (int s = 0; s < 4; s++) {
            uint32_t aH[2][4], aL[2][4];
#pragma unroll
            for (int mt = 0; mt < 2; mt++) {
                int row  = warp_m * 32 + mt * 16 + (lane & 7) + ((lane >> 3) & 1) * 8;
                int unit = s * 2 + (lane >> 4);
                uint32_t addr = sb + SW128(row * 128 + unit * 16);
                LDSM_X4(aH[mt], addr);
                LDSM_X4(aL[mt], addr + 16384);
            }
            uint32_t bH[8][2], bL[8][2];
#pragma unroll
            for (int np = 0; np < 4; np++) {
                int row  = warp_n * 64 + np * 16 + ((lane >> 4) & 1) * 8 + (lane & 7);
                int unit = s * 2 + ((lane >> 3) & 1);
                uint32_t addr = sb + 32768 + SW128(row * 128 + unit * 16);
                uint32_t tmp[4];
                LDSM_X4(tmp, addr);
                bH[2*np][0] = tmp[0]; bH[2*np][1] = tmp[1];
                bH[2*np+1][0] = tmp[2]; bH[2*np+1][1] = tmp[3];
                LDSM_X4(tmp, addr + 16384);
                bL[2*np][0] = tmp[0]; bL[2*np][1] = tmp[1];
                bL[2*np+1][0] = tmp[2]; bL[2*np+1][1] = tmp[3];
            }
#pragma unroll
            for (int mt = 0; mt < 2; mt++)
#pragma unroll
                for (int nt = 0; nt < 8; nt++) {
                    MMA16816(d[mt][nt], aH[mt], bH[nt][0], bH[nt][1]);
                    MMA16816(d[mt][nt], aH[mt], bL[nt][0], bL[nt][1]);
                    MMA16816(d[mt][nt], aL[mt], bH[nt][0], bH[nt][1]);
                }
        }
        __syncthreads();
    }

    const bool vstore = (mode == 3) && (blockIdx.x >= 24);
    if (!vstore) {
#pragma unroll
        for (int mt = 0; mt < 2; mt++) {
#pragma unroll
            for (int nt = 0; nt < 8; nt++) {
                int row = m0 + warp_m * 32 + mt * 16 + (lane >> 2);
                int col = n0 + warp_n * 64 + nt * 8 + (lane & 3) * 2;
                *(float2*)&C[(size_t)row * Nc + col] =
                    make_float2(d[mt][nt][0], d[mt][nt][1]);
                *(float2*)&C[(size_t)(row + 8) * Nc + col] =
                    make_float2(d[mt][nt][2], d[mt][nt][3]);
            }
        }
    } else {
        // V split store: head-major, col relative to V block start (3072)
#pragma unroll
        for (int mt = 0; mt < 2; mt++) {
#pragma unroll
            for (int nt = 0; nt < 8; nt++) {
                int row = m0 + warp_m * 32 + mt * 16 + (lane >> 2);
                int col = n0 - 3072 + warp_n * 64 + nt * 8 + (lane & 3) * 2;
                int bq = row >> 11, t = row & 2047;
                int kv = col >> 7, h = col & 127;
                size_t o0 = ((size_t)(bq * Kk + kv) * Tt + t) * Hh + h;
                size_t o1 = ((size_t)(bq * Kk + kv) * Tt + t + 8) * Hh + h;
                uint32_t lop;
                uint32_t hip = split2(d[mt][nt][0], d[mt][nt][1], lop);
                *(uint32_t*)(Oh + o0) = hip;
                *(uint32_t*)(Ol + o0) = lop;
                hip = split2(d[mt][nt][2], d[mt][nt][3], lop);
                *(uint32_t*)(Oh + o1) = hip;
                *(uint32_t*)(Ol + o1) = lop;
            }
        }
    }
#undef ISSUE_CHUNK
}

// ---------------------------------------------------------------------------
// RMSNorm + RoPE(table) + bf16 split + head-major store.
// Reads from g_qkv combined buffer at column offset col0.
// ---------------------------------------------------------------------------
__global__ __launch_bounds__(128)
void norm_rope_split(const float* __restrict__ in, const float* __restrict__ scale,
                     __nv_bfloat16* __restrict__ outhi, __nv_bfloat16* __restrict__ outlo,
                     int heads, int col0, float post_scale) {
    const int row  = blockIdx.x;
    const int h    = threadIdx.x;
    const int trow = row / heads;
    const int n    = row - trow * heads;
    const int b    = trow >> 11;
    const int t    = trow & 2047;

    float v = in[(size_t)trow * 4096 + col0 + n * Hh + h];
    float ss = v * v;
#pragma unroll
    for (int o = 16; o; o >>= 1) ss += __shfl_xor_sync(0xffffffffu, ss, o);
    __shared__ float warpsum[4];
    __shared__ float s_n[Hh];
    if ((h & 31) == 0) warpsum[h >> 5] = ss;
    __syncthreads();
    float total = warpsum[0] + warpsum[1] + warpsum[2] + warpsum[3];
    float inv_rms = rsqrtf(total * (1.0f / 128.0f) + EPSf);
    s_n[h] = v * inv_rms * scale[h];
    __syncthreads();

    float2 sc = g_rope[(size_t)trow * 64 + (h & 63)];
    float out = (h < 64) ? (s_n[h] * sc.y - s_n[h + 64] * sc.x)
                         : (s_n[h] * sc.y + s_n[h - 64] * sc.x);
    out *= post_scale;
    __nv_bfloat16 hi = __float2bfloat16(out);
    __nv_bfloat16 lo = __float2bfloat16(out - __bfloat162float(hi));
    size_t o = ((size_t)(b * heads + n) * Tt + t) * Hh + h;
    outhi[o] = hi;
    outlo[o] = lo;
}

// ---------------------------------------------------------------------------
// HMMA flash attention, GQA-paired (one CTA per kv-head, both q-heads).
// ---------------------------------------------------------------------------
#define AT_ST0  65536
#define AT_POS  196608
#define AT_SEG  204800
#define AT_META 212992
#define ATT_SMEM (212992 + 512)

__global__ __launch_bounds__(256)
void attn_hmma(const int* __restrict__ seg_g) {
    extern __shared__ char sm[];
    const uint32_t sb = smem_u32(sm);
    int* sPos  = (int*)(sm + AT_POS);
    int* sSeg  = (int*)(sm + AT_SEG);
    int* sKmin = (int*)(sm + AT_META);
    int* sTiles = sKmin + 32;
    int* sCtl   = sTiles + 32;

    const int tid = threadIdx.x, lane = tid & 31, warp = tid >> 5;
    const int qbase = blockIdx.x * 64;
    const int kvh = blockIdx.y, b = blockIdx.z;
    const int hsel = warp >> 2;
    const int mwarp = warp & 3;
    const int n = kvh * 2 + hsel;

    for (int i = tid; i < 2048; i += 256) {
        sPos[i] = g_pos[b * Tt + i];
        sSeg[i] = seg_g[b * Tt + i];
    }
    for (int i = tid; i < 2048; i += 256) {
        int hh = i >> 10;
        int j = i & 1023;
        int r = j >> 4, u = j & 15;
        uint32_t off = hh * 32768 + ((u >> 3) << 13) + SW128(r * 128 + (u & 7) * 16);
        const char* qh = (const char*)(g_qhh + ((size_t)(b * Nn + kvh * 2 + hh) * Tt + qbase) * Hh);
        const char* ql = (const char*)(g_qhl + ((size_t)(b * Nn + kvh * 2 + hh) * Tt + qbase) * Hh);
        *(uint4*)(sm + off)         = *(const uint4*)(qh + r * 256 + u * 16);
        *(uint4*)(sm + 16384 + off) = *(const uint4*)(ql + r * 256 + u * 16);
    }
    __syncthreads();

    {
#pragma unroll
        for (int j = 0; j < 4; j++) {
            int tt = warp * 4 + j;
            int mn = min(sPos[tt * 64 + lane], sPos[tt * 64 + 32 + lane]);
#pragma unroll
            for (int o = 16; o; o >>= 1) mn = min(mn, __shfl_xor_sync(0xffffffffu, mn, o));
            if (lane == 0) sKmin[tt] = mn;
        }
        if (warp == 0) {
            int v = max(sPos[qbase + lane], sPos[qbase + 32 + lane]);
#pragma unroll
            for (int o = 16; o; o >>= 1) v = max(v, __shfl_xor_sync(0xffffffffu, v, o));
            if (lane == 0) sCtl[0] = v;
        }
    }
    __syncthreads();
    if (tid == 0) {
        int qmax = sCtl[0], na = 0;
        for (int tt = 0; tt < 32; tt++)
            if (sKmin[tt] <= qmax) sTiles[na++] = tt;
        sCtl[1] = na;
    }
    __syncthreads();
    const int nactive = sCtl[1];

    const char* kh = (const char*)(g_khh + ((size_t)(b * Kk + kvh) * Tt) * Hh);
    const char* kl = (const char*)(g_khl + ((size_t)(b * Kk + kvh) * Tt) * Hh);
    const char* vh = (const char*)(g_vhh + ((size_t)(b * Kk + kvh) * Tt) * Hh);
    const char* vl = (const char*)(g_vhl + ((size_t)(b * Kk + kvh) * Tt) * Hh);

#define AT_ISSUE(tt, st) do {                                                \
    const int sbase_ = (tt) * 64;                                            \
    uint32_t stb = sb + AT_ST0 + (st) * 65536;                               \
    for (int i = tid; i < 1024; i += 256) {                                  \
        int r = i >> 4, u = i & 15;                                          \
        uint32_t off = ((u >> 3) << 13) + SW128(r * 128 + (u & 7) * 16);     \
        size_t go = (size_t)(sbase_ + r) * 256 + u * 16;                     \
        CP_ASYNC16(stb + off,         kh + go);                              \
        CP_ASYNC16(stb + 16384 + off, kl + go);                              \
        CP_ASYNC16(stb + 32768 + off, vh + go);                              \
        CP_ASYNC16(stb + 49152 + off, vl + go);                              \
    }                                                                        \
} while (0)

    const int r_lo = mwarp * 16 + (lane >> 2);
    const int qp0 = sPos[qbase + r_lo];
    const int qp1 = sPos[qbase + r_lo + 8];
    const int qs0 = sSeg[qbase + r_lo];
    const int qs1 = sSeg[qbase + r_lo + 8];

    float d_o[16][4];
#pragma unroll
    for (int nt = 0; nt < 16; nt++)
#pragma unroll
        for (int j = 0; j < 4; j++) d_o[nt][j] = 0.f;
    float m0 = -1e30f, m1 = -1e30f, l0 = 0.f, l1 = 0.f;

    const int qrow_l = mwarp * 16 + (lane & 7) + ((lane >> 3) & 1) * 8;
    const int krow_l = ((lane >> 4) & 1) * 8 + (lane & 7);
    const int vrow_l = (((lane >> 3) & 1) << 3) + (lane & 7);
    const int qh_sel = (lane >> 4) << 3;
    const int kh_sel = ((lane >> 3) & 1) << 3;
    const int vh_sel = (lane >> 4) << 3;
    const uint32_t qpanel = sb + hsel * 32768;

    if (nactive > 0) { AT_ISSUE(sTiles[0], 0); CP_COMMIT(); }

    for (int j = 0; j < nactive; j++) {
        const int tt = sTiles[j];
        const int sbase = tt * 64;
        if (j + 1 < nactive) { AT_ISSUE(sTiles[j + 1], (j + 1) & 1); CP_COMMIT(); CP_WAIT(1); }
        else                 { CP_WAIT(0); }
        __syncthreads();

        const uint32_t stb = sb + AT_ST0 + (j & 1) * 65536;

        float ds[8][4];
#pragma unroll
        for (int nt = 0; nt < 8; nt++)
#pragma unroll
            for (int jj = 0; jj < 4; jj++) ds[nt][jj] = 0.f;

#pragma unroll
        for (int ks = 0; ks < 8; ks++) {
            int hq = ks * 16 + qh_sel;
            uint32_t qoff = ((hq >> 6) << 13) + SW128(qrow_l * 128 + ((hq & 63) << 1));
            uint32_t aH[4], aL[4];
            LDSM_X4(aH, qpanel + qoff);
            LDSM_X4(aL, qpanel + 16384 + qoff);
            int hk = ks * 16 + kh_sel;
            uint32_t kpan = ((hk >> 6) << 13);
            uint32_t kcol = (hk & 63) << 1;
#pragma unroll
            for (int np = 0; np < 4; np++) {
                uint32_t addr = stb + kpan + SW128((np * 16 + krow_l) * 128 + kcol);
                uint32_t tH[4], tL[4];
                LDSM_X4(tH, addr);
                LDSM_X4(tL, addr + 16384);
                MMA16816(ds[2*np],   aH, tH[0], tH[1]);
                MMA16816(ds[2*np],   aH, tL[0], tL[1]);
                MMA16816(ds[2*np],   aL, tH[0], tH[1]);
                MMA16816(ds[2*np+1], aH, tH[2], tH[3]);
                MMA16816(ds[2*np+1], aH, tL[2], tL[3]);
                MMA16816(ds[2*np+1], aL, tH[2], tH[3]);
            }
        }

#pragma unroll
        for (int nt = 0; nt < 8; nt++) {
            int c = sbase + nt * 8 + (lane & 3) * 2;
            int kp0 = sPos[c], kp1 = sPos[c + 1];
            int ks0 = sSeg[c], ks1 = sSeg[c + 1];
            if (!(kp0 <= qp0 && ks0 == qs0)) ds[nt][0] = -1e30f;
            if (!(kp1 <= qp0 && ks1 == qs0)) ds[nt][1] = -1e30f;
            if (!(kp0 <= qp1 && ks0 == qs1)) ds[nt][2] = -1e30f;
            if (!(kp1 <= qp1 && ks1 == qs1)) ds[nt][3] = -1e30f;
        }

        float tm0 = -1e30f, tm1 = -1e30f;
#pragma unroll
        for (int nt = 0; nt < 8; nt++) {
            tm0 = fmaxf(tm0, fmaxf(ds[nt][0], ds[nt][1]));
            tm1 = fmaxf(tm1, fmaxf(ds[nt][2], ds[nt][3]));
        }
        tm0 = fmaxf(tm0, __shfl_xor_sync(0xffffffffu, tm0, 1));
        tm0 = fmaxf(tm0, __shfl_xor_sync(0xffffffffu, tm0, 2));
        tm1 = fmaxf(tm1, __shfl_xor_sync(0xffffffffu, tm1, 1));
        tm1 = fmaxf(tm1, __shfl_xor_sync(0xffffffffu, tm1, 2));
        float nm0 = fmaxf(m0, tm0), nm1 = fmaxf(m1, tm1);
        float a0 = __expf(m0 - nm0), a1 = __expf(m1 - nm1);
        float gg0 = (nm0 > -0.9e30f) ? 1.f : 0.f;
        float gg1 = (nm1 > -0.9e30f) ? 1.f : 0.f;
        float s0 = 0.f, s1 = 0.f;
#pragma unroll
        for (int nt = 0; nt < 8; nt++) {
            ds[nt][0] = gg0 * __expf(ds[nt][0] - nm0);
            ds[nt][1] = gg0 * __expf(ds[nt][1] - nm0);
            ds[nt][2] = gg1 * __expf(ds[nt][2] - nm1);
            ds[nt][3] = gg1 * __expf(ds[nt][3] - nm1);
            s0 += ds[nt][0] + ds[nt][1];
            s1 += ds[nt][2] + ds[nt][3];
        }
        s0 += __shfl_xor_sync(0xffffffffu, s0, 1);
        s0 += __shfl_xor_sync(0xffffffffu, s0, 2);
        s1 += __shfl_xor_sync(0xffffffffu, s1, 1);
        s1 += __shfl_xor_sync(0xffffffffu, s1, 2);
        l0 = l0 * a0 + s0; m0 = nm0;
        l1 = l1 * a1 + s1; m1 = nm1;
#pragma unroll
        for (int nt = 0; nt < 16; nt++) {
            d_o[nt][0] *= a0; d_o[nt][1] *= a0;
            d_o[nt][2] *= a1; d_o[nt][3] *= a1;
        }

        uint32_t Ph[4][4], Pl[4][4];
#pragma unroll
        for (int kb = 0; kb < 4; kb++) {
            Ph[kb][0] = split2(ds[2*kb][0],   ds[2*kb][1],   Pl[kb][0]);
            Ph[kb][1] = split2(ds[2*kb][2],   ds[2*kb][3],   Pl[kb][1]);
            Ph[kb][2] = split2(ds[2*kb+1][0], ds[2*kb+1][1], Pl[kb][2]);
            Ph[kb][3] = split2(ds[2*kb+1][2], ds[2*kb+1][3], Pl[kb][3]);
        }

#pragma unroll
        for (int ntp = 0; ntp < 8; ntp++) {
            int hv = ntp * 16 + vh_sel;
            uint32_t vpan = ((hv >> 6) << 13);
            uint32_t vcol = (hv & 63) << 1;
#pragma unroll
            for (int kb = 0; kb < 4; kb++) {
                uint32_t addr = stb + 32768 + vpan + SW128((kb * 16 + vrow_l) * 128 + vcol);
                uint32_t tH[4], tL[4];
                LDSM_X4_T(tH, addr);
                LDSM_X4_T(tL, addr + 16384);
                MMA16816(d_o[2*ntp],   Ph[kb], tH[0], tH[1]);
                MMA16816(d_o[2*ntp],   Pl[kb], tH[0], tH[1]);
                MMA16816(d_o[2*ntp],   Ph[kb], tL[0], tL[1]);
                MMA16816(d_o[2*ntp+1], Ph[kb], tH[2], tH[3]);
                MMA16816(d_o[2*ntp+1], Pl[kb], tH[2], tH[3]);
                MMA16816(d_o[2*ntp+1], Ph[kb], tL[2], tL[3]);
            }
        }
        __syncthreads();
    }
#undef AT_ISSUE

    float il0 = (l0 > 0.f) ? (1.f / l0) : 0.f;
    float il1 = (l1 > 0.f) ? (1.f / l1) : 0.f;
    size_t base0 = ((size_t)(b * Tt + qbase + r_lo))     * 2048 + n * 128;
    size_t base1 = ((size_t)(b * Tt + qbase + r_lo + 8)) * 2048 + n * 128;
#pragma unroll
    for (int nt = 0; nt < 16; nt++) {
        int h = nt * 8 + (lane & 3) * 2;
        uint32_t lop;
        uint32_t hip = split2(d_o[nt][0] * il0, d_o[nt][1] * il0, lop);
        *(uint32_t*)(g_atthi + base0 + h) = hip;
        *(uint32_t*)(g_attlo + base0 + h) = lop;
        hip = split2(d_o[nt][2] * il1, d_o[nt][3] * il1, lop);
        *(uint32_t*)(g_atthi + base1 + h) = hip;
        *(uint32_t*)(g_attlo + base1 + h) = lop;
    }
}

// ---------------------------------------------------------------------------
extern "C" void kernel_launch(void* const* d_in, const int* in_sizes, int n_in,
                              void* d_out, int out_size) {
    const float* x       = (const float*)d_in[0];
    const int*   seg     = (const int*)  d_in[1];
    const float* wq      = (const float*)d_in[2];
    const float* wk      = (const float*)d_in[3];
    const float* wv      = (const float*)d_in[4];
    const float* wo      = (const float*)d_in[5];
    const float* q_scale = (const float*)d_in[6];
    const float* k_scale = (const float*)d_in[7];
    float* out = (float*)d_out;

    float* qkv;
    cudaGetSymbolAddress((void**)&qkv, g_qkv);
    __nv_bfloat16 *xhi, *xlo, *ahi, *alo;
    __nv_bfloat16 *wch, *wcl, *woh, *wol;
    __nv_bfloat16 *qhh, *qhl, *khh, *khl, *vhh, *vhl;
    cudaGetSymbolAddress((void**)&xhi, g_xhi);
    cudaGetSymbolAddress((void**)&xlo, g_xlo);
    cudaGetSymbolAddress((void**)&ahi, g_atthi);
    cudaGetSymbolAddress((void**)&alo, g_attlo);
    cudaGetSymbolAddress((void**)&wch, g_wqkvT_hi);
    cudaGetSymbolAddress((void**)&wcl, g_wqkvT_lo);
    cudaGetSymbolAddress((void**)&woh, g_woT_hi);
    cudaGetSymbolAddress((void**)&wol, g_woT_lo);
    cudaGetSymbolAddress((void**)&qhh, g_qhh);
    cudaGetSymbolAddress((void**)&qhl, g_qhl);
    cudaGetSymbolAddress((void**)&khh, g_khh);
    cudaGetSymbolAddress((void**)&khl, g_khl);
    cudaGetSymbolAddress((void**)&vhh, g_vhh);
    cudaGetSymbolAddress((void**)&vhl, g_vhl);

    cudaFuncSetAttribute(gemm_hmma, cudaFuncAttributeMaxDynamicSharedMemorySize,
                         GEMM_SMEM);
    cudaFuncSetAttribute(attn_hmma, cudaFuncAttributeMaxDynamicSharedMemorySize,
                         ATT_SMEM);

    pos_kernel<<<Bb, 256>>>(seg);
    rope_kernel<<<Mrows * 64 / 256, 256>>>();

    // split conversions (wq/wk/wv into one concatenated transposed buffer)
    conv_split<<<1024, 256>>>(x, xhi, xlo, (size_t)Mrows * Dd / 4);
    conv_tsplit<<<dim3(2048 / 32, 1024 / 32), dim3(32, 8)>>>(
        wq, wch, wcl, 1024, 2048);
    conv_tsplit<<<dim3(1024 / 32, 1024 / 32), dim3(32, 8)>>>(
        wk, wch + (size_t)2048 * 1024, wcl + (size_t)2048 * 1024, 1024, 1024);
    conv_tsplit<<<dim3(1024 / 32, 1024 / 32), dim3(32, 8)>>>(
        wv, wch + (size_t)3072 * 1024, wcl + (size_t)3072 * 1024, 1024, 1024);
    conv_tsplit<<<dim3(1024 / 32, 2048 / 32), dim3(32, 8)>>>(wo, woh, wol, 2048, 1024);

    // Combined QKV projection: q|k fp32 -> g_qkv, v -> split head-major
    gemm_hmma<<<dim3(32, Mrows / 128), 256, GEMM_SMEM>>>(
        xhi, xlo, wch, wcl, qkv, vhh, vhl, 3, 4096, 1024);

    // RMSNorm + RoPE(table) + split (q pre-scaled by SCALE)
    norm_rope_split<<<Mrows * Nn, 128>>>(qkv, q_scale, qhh, qhl, Nn, 0, SCALEf);
    norm_rope_split<<<Mrows * Kk, 128>>>(qkv, k_scale, khh, khl, Kk, 2048, 1.0f);

    // HMMA flash attention (GQA-paired, cp.async pipelined)
    attn_hmma<<<dim3(Tt / 64, Kk, Bb), 256, ATT_SMEM>>>(seg);

    // output projection (fp32 store to d_out)
    gemm_hmma<<<dim3(1024 / 128, Mrows / 128), 256, GEMM_SMEM>>>(
        ahi, alo, woh, wol, out, (__nv_bfloat16*)0, (__nv_bfloat16*)0, 0, 1024, 2048);
}

// round 11
// speedup vs baseline: 1.1226x; 1.0194x over previous
#include <cuda_runtime.h>
#include <cuda_bf16.h>
#include <math.h>
#include <float.h>
#include <limits.h>
#include <stdint.h>

// Problem constants
#define Bb 2
#define Tt 2048
#define Dd 1024
#define Nn 16
#define Kk 8
#define Hh 128
#define Gg 2
#define Mrows (Bb*Tt)          // 4096

static constexpr float EPSf   = 1e-6f;
static constexpr float LOG_THETA = 13.815510557964274f;  // ln(1e6)
static constexpr float SCALEf = 0.08838834764831845f;    // 128^-0.5

// ---------------------------------------------------------------------------
// Scratch (allocation-free rule: __device__ globals)
// ---------------------------------------------------------------------------
__device__ int    g_pos[Mrows];
__device__ float2 g_rope[(size_t)Mrows * 64];            // (sin, cos) per (row, i)
__device__ float  g_qkv[(size_t)Mrows * 4096];           // fp32 q|k cols 0..3071

// bf16 split buffers
__device__ __nv_bfloat16 g_xhi[(size_t)Mrows * Dd];
__device__ __nv_bfloat16 g_xlo[(size_t)Mrows * Dd];
__device__ __nv_bfloat16 g_atthi[(size_t)Mrows * Nn * Hh];   // attn out [row][n*H]
__device__ __nv_bfloat16 g_attlo[(size_t)Mrows * Nn * Hh];
__device__ __nv_bfloat16 g_wqkvT_hi[(size_t)4096 * Dd];      // [wq|wk|wv]^T rows
__device__ __nv_bfloat16 g_wqkvT_lo[(size_t)4096 * Dd];
__device__ __nv_bfloat16 g_woT_hi[(size_t)Dd * (Nn*Hh)];
__device__ __nv_bfloat16 g_woT_lo[(size_t)Dd * (Nn*Hh)];

// head-major bf16 split q/k/v for attention: [b][head][t][h]
__device__ __nv_bfloat16 g_qhh[(size_t)Bb * Nn * Tt * Hh];
__device__ __nv_bfloat16 g_qhl[(size_t)Bb * Nn * Tt * Hh];
__device__ __nv_bfloat16 g_khh[(size_t)Bb * Kk * Tt * Hh];
__device__ __nv_bfloat16 g_khl[(size_t)Bb * Kk * Tt * Hh];
__device__ __nv_bfloat16 g_vhh[(size_t)Bb * Kk * Tt * Hh];
__device__ __nv_bfloat16 g_vhl[(size_t)Bb * Kk * Tt * Hh];

// ---------------------------------------------------------------------------
// PTX helpers (sm_103 baseline ISA: cp.async, ldmatrix, mma.sync)
// ---------------------------------------------------------------------------
__device__ __forceinline__ uint32_t smem_u32(const void* p) {
    uint32_t a;
    asm("{ .reg .u64 t; cvta.to.shared.u64 t, %1; cvt.u32.u64 %0, t; }"
        : "=r"(a) : "l"(p));
    return a;
}
#define SW128(off) ((off) ^ (((off) >> 3) & 0x70))

#define CP_ASYNC16(saddr, gaddr) \
    asm volatile("cp.async.cg.shared.global [%0], [%1], 16;" \
        :: "r"(saddr), "l"(gaddr) : "memory")
#define CP_COMMIT() asm volatile("cp.async.commit_group;" ::: "memory")
#define CP_WAIT(n)  asm volatile("cp.async.wait_group %0;" :: "n"(n) : "memory")

#define LDSM_X4(r, addr) \
    asm volatile("ldmatrix.sync.aligned.m8n8.x4.shared.b16 {%0,%1,%2,%3}, [%4];" \
        : "=r"((r)[0]), "=r"((r)[1]), "=r"((r)[2]), "=r"((r)[3]) : "r"(addr))
#define LDSM_X4_T(r, addr) \
    asm volatile("ldmatrix.sync.aligned.m8n8.x4.trans.shared.b16 {%0,%1,%2,%3}, [%4];" \
        : "=r"((r)[0]), "=r"((r)[1]), "=r"((r)[2]), "=r"((r)[3]) : "r"(addr))

#define MMA16816(d, a, b0r, b1r) \
    asm volatile("mma.sync.aligned.m16n8k16.row.col.f32.bf16.bf16.f32 " \
        "{%0,%1,%2,%3}, {%4,%5,%6,%7}, {%8,%9}, {%0,%1,%2,%3};" \
        : "+f"((d)[0]), "+f"((d)[1]), "+f"((d)[2]), "+f"((d)[3]) \
        : "r"((a)[0]), "r"((a)[1]), "r"((a)[2]), "r"((a)[3]), \
          "r"((b0r)), "r"((b1r)))

// Split fp32 pair into packed bf16 hi + packed bf16 residual.
__device__ __forceinline__ uint32_t split2(float x0, float x1, uint32_t& lopack) {
    __nv_bfloat16 h0 = __float2bfloat16(x0), h1 = __float2bfloat16(x1);
    float r0 = x0 - __bfloat162float(h0), r1 = x1 - __bfloat162float(h1);
    __nv_bfloat16 g0 = __float2bfloat16(r0), g1 = __float2bfloat16(r1);
    lopack = (uint32_t)__bfloat16_as_ushort(g0) | ((uint32_t)__bfloat16_as_ushort(g1) << 16);
    return (uint32_t)__bfloat16_as_ushort(h0) | ((uint32_t)__bfloat16_as_ushort(h1) << 16);
}

// ---------------------------------------------------------------------------
// positions_from_segment_ids
// ---------------------------------------------------------------------------
__global__ void pos_kernel(const int* __restrict__ seg) {
    int b = blockIdx.x;
    int tid = threadIdx.x;
    __shared__ int sv[256], si[256];
    int bv = INT_MIN, bi = INT_MAX;
    for (int t = tid; t < Tt; t += 256) {
        int v = seg[b * Tt + t];
        if (v > bv) { bv = v; bi = t; }
    }
    sv[tid] = bv; si[tid] = bi;
    __syncthreads();
    for (int o = 128; o; o >>= 1) {
        if (tid < o) {
            if (sv[tid + o] > sv[tid] ||
                (sv[tid + o] == sv[tid] && si[tid + o] < si[tid])) {
                sv[tid] = sv[tid + o]; si[tid] = si[tid + o];
            }
        }
        __syncthreads();
    }
    int off = si[0];
    for (int t = tid; t < Tt; t += 256) {
        int v = seg[b * Tt + t];
        g_pos[b * Tt + t] = (v != 0) ? (t - off) : (1 << 30);
    }
}

// ---------------------------------------------------------------------------
// RoPE sin/cos table: g_rope[row*64 + i]
// ---------------------------------------------------------------------------
__global__ __launch_bounds__(256)
void rope_kernel() {
    int idx = blockIdx.x * 256 + threadIdx.x;     // Mrows*64
    int gr = idx >> 6, i = idx & 63;
    int pos = g_pos[gr];
    float inv_freq = __expf(-(float)i * (LOG_THETA / 64.0f));
    float ang = (float)pos * inv_freq;
    g_rope[idx] = make_float2(sinf(ang), cosf(ang));
}

// ---------------------------------------------------------------------------
// fp32 -> (hi, lo) bf16 split, elementwise
// ---------------------------------------------------------------------------
__global__ __launch_bounds__(256)
void conv_split(const float* __restrict__ src, __nv_bfloat16* __restrict__ hi,
                __nv_bfloat16* __restrict__ lo, size_t n4) {
    size_t i = (size_t)blockIdx.x * blockDim.x + threadIdx.x;
    size_t stride = (size_t)gridDim.x * blockDim.x;
    for (; i < n4; i += stride) {
        float4 v = ((const float4*)src)[i];
        uint32_t l01, l23;
        uint32_t h01 = split2(v.x, v.y, l01);
        uint32_t h23 = split2(v.z, v.w, l23);
        ((uint2*)hi)[i] = make_uint2(h01, h23);
        ((uint2*)lo)[i] = make_uint2(l01, l23);
    }
}

// ---------------------------------------------------------------------------
// Transpose + split: w[Kd, Nc] fp32 -> wT_hi/lo[Nc, Kd] bf16
// ---------------------------------------------------------------------------
__global__ __launch_bounds__(256)
void conv_tsplit(const float* __restrict__ w, __nv_bfloat16* __restrict__ hi,
                 __nv_bfloat16* __restrict__ lo, int Kd, int Nc) {
    __shared__ float t[32][33];
    int n0 = blockIdx.x * 32, k0 = blockIdx.y * 32;
    int tx = threadIdx.x, ty = threadIdx.y;
    for (int i = ty; i < 32; i += 8)
        t[i][tx] = w[(size_t)(k0 + i) * Nc + n0 + tx];
    __syncthreads();
    for (int i = ty; i < 32; i += 8) {
        float v = t[tx][i];
        __nv_bfloat16 h = __float2bfloat16(v);
        __nv_bfloat16 l = __float2bfloat16(v - __bfloat162float(h));
        size_t o = (size_t)(n0 + i) * Kd + k0 + tx;
        hi[o] = h; lo[o] = l;
    }
}

// ---------------------------------------------------------------------------
// HMMA bf16-split GEMM, 256x128 CTA tile, 8 warps (4m x 2n of 64x64),
// BK=64, 2-stage cp.async pipeline.
// smem stage layout: Ahi[0,32K) Alo[32K,64K) Bhi[64K,80K) Blo[80K,96K)
// mode 0: fp32 store to C
// mode 3: combined QKV: col tiles 0..23 -> fp32 (q|k), 24..31 -> V split
// ---------------------------------------------------------------------------
#define GSTAGE  98304
#define GA_LO   32768
#define GB_HI   65536
#define GB_LO   81920
#define GEMM_SMEM (2 * GSTAGE)

__global__ __launch_bounds__(256)
void gemm_hmma(const __nv_bfloat16* __restrict__ Ahi, const __nv_bfloat16* __restrict__ Alo,
               const __nv_bfloat16* __restrict__ Bhi, const __nv_bfloat16* __restrict__ Blo,
               float* __restrict__ C,
               __nv_bfloat16* __restrict__ Oh, __nv_bfloat16* __restrict__ Ol,
               int mode, int Nc, int Kd) {
    extern __shared__ char smc[];
    const int tid  = threadIdx.x;
    const int lane = tid & 31;
    const int wid  = tid >> 5;
    const int warp_m = wid & 3;            // 64-row slab
    const int warp_n = wid >> 2;           // 64-col slab
    const int m0 = blockIdx.y * 256, n0 = blockIdx.x * 128;

    const int u = tid & 7;
    const int r = tid >> 3;                // 0..31

    const uint32_t sbase = smem_u32(smc);
    const int nchunk = Kd >> 6;

    float d[4][8][4];
#pragma unroll
    for (int mt = 0; mt < 4; mt++)
#pragma unroll
        for (int nt = 0; nt < 8; nt++)
#pragma unroll
            for (int j = 0; j < 4; j++) d[mt][nt][j] = 0.f;

#define ISSUE_CHUNK(c, s) do {                                               \
    const int k0e = (c) * 64;                                                \
    uint32_t sa = sbase + (s) * GSTAGE;                                      \
    _Pragma("unroll")                                                        \
    for (int i = 0; i < 8; i++) {                                            \
        int row = r + i * 32;                                                \
        uint32_t so = SW128(row * 128 + u * 16);                             \
        CP_ASYNC16(sa + so,         Ahi + (size_t)(m0 + row) * Kd + k0e + u * 8); \
        CP_ASYNC16(sa + GA_LO + so, Alo + (size_t)(m0 + row) * Kd + k0e + u * 8); \
    }                                                                        \
    _Pragma("unroll")                                                        \
    for (int i = 0; i < 4; i++) {                                            \
        int row = r + i * 32;                                                \
        uint32_t so = SW128(row * 128 + u * 16);                             \
        CP_ASYNC16(sa + GB_HI + so, Bhi + (size_t)(n0 + row) * Kd + k0e + u * 8); \
        CP_ASYNC16(sa + GB_LO + so, Blo + (size_t)(n0 + row) * Kd + k0e + u * 8); \
    }                                                                        \
} while (0)

    ISSUE_CHUNK(0, 0);
    CP_COMMIT();

    for (int c = 0; c < nchunk; c++) {
        if (c + 1 < nchunk) { ISSUE_CHUNK(c + 1, (c + 1) & 1); CP_COMMIT(); CP_WAIT(1); }
        else                { CP_WAIT(0); }
        __syncthreads();

        const uint32_t sb = sbase + (c & 1) * GSTAGE;
#pragma unroll
        for (int s = 0; s < 4; s++) {
            uint32_t bH[8][2], bL[8][2];
#pragma unroll
            for (int np = 0; np < 4; np++) {
                int row  = warp_n * 64 + np * 16 + ((lane >> 4) & 1) * 8 + (lane & 7);
                int unit = s * 2 + ((lane >> 3) & 1);
                uint32_t addr = sb + GB_HI + SW128(row * 128 + unit * 16);
                uint32_t tmp[4];
                LDSM_X4(tmp, addr);
                bH[2*np][0] = tmp[0]; bH[2*np][1] = tmp[1];
                bH[2*np+1][0] = tmp[2]; bH[2*np+1][1] = tmp[3];
                LDSM_X4(tmp, addr + 16384);
                bL[2*np][0] = tmp[0]; bL[2*np][1] = tmp[1];
                bL[2*np+1][0] = tmp[2]; bL[2*np+1][1] = tmp[3];
            }
#pragma unroll
            for (int mt = 0; mt < 4; mt++) {
                uint32_t aH[4], aL[4];
                int row  = warp_m * 64 + mt * 16 + (lane & 7) + ((lane >> 3) & 1) * 8;
                int unit = s * 2 + (lane >> 4);
                uint32_t addr = sb + SW128(row * 128 + unit * 16);
                LDSM_X4(aH, addr);
                LDSM_X4(aL, addr + GA_LO);
#pragma unroll
                for (int nt = 0; nt < 8; nt++) {
                    MMA16816(d[mt][nt], aH, bH[nt][0], bH[nt][1]);
                    MMA16816(d[mt][nt], aH, bL[nt][0], bL[nt][1]);
                    MMA16816(d[mt][nt], aL, bH[nt][0], bH[nt][1]);
                }
            }
        }
        __syncthreads();
    }

    const bool vstore = (mode == 3) && (blockIdx.x >= 24);
    if (!vstore) {
#pragma unroll
        for (int mt = 0; mt < 4; mt++) {
#pragma unroll
            for (int nt = 0; nt < 8; nt++) {
                int row = m0 + warp_m * 64 + mt * 16 + (lane >> 2);
                int col = n0 + warp_n * 64 + nt * 8 + (lane & 3) * 2;
                *(float2*)&C[(size_t)row * Nc + col] =
                    make_float2(d[mt][nt][0], d[mt][nt][1]);
                *(float2*)&C[(size_t)(row + 8) * Nc + col] =
                    make_float2(d[mt][nt][2], d[mt][nt][3]);
            }
        }
    } else {
        // V split store: head-major, col relative to V block start (3072)
#pragma unroll
        for (int mt = 0; mt < 4; mt++) {
#pragma unroll
            for (int nt = 0; nt < 8; nt++) {
                int row = m0 + warp_m * 64 + mt * 16 + (lane >> 2);
                int col = n0 - 3072 + warp_n * 64 + nt * 8 + (lane & 3) * 2;
                int bq = row >> 11, t = row & 2047;
                int kv = col >> 7, h = col & 127;
                size_t o0 = ((size_t)(bq * Kk + kv) * Tt + t) * Hh + h;
                size_t o1 = ((size_t)(bq * Kk + kv) * Tt + t + 8) * Hh + h;
                uint32_t lop;
                uint32_t hip = split2(d[mt][nt][0], d[mt][nt][1], lop);
                *(uint32_t*)(Oh + o0) = hip;
                *(uint32_t*)(Ol + o0) = lop;
                hip = split2(d[mt][nt][2], d[mt][nt][3], lop);
                *(uint32_t*)(Oh + o1) = hip;
                *(uint32_t*)(Ol + o1) = lop;
            }
        }
    }
#undef ISSUE_CHUNK
}

// ---------------------------------------------------------------------------
// RMSNorm + RoPE(table) + bf16 split + head-major store (q and k in one grid).
// blocks [0, Mrows*Nn) -> q, [Mrows*Nn, Mrows*(Nn+Kk)) -> k
// ---------------------------------------------------------------------------
__global__ __launch_bounds__(128)
void norm_rope_split(const float* __restrict__ in,
                     const float* __restrict__ q_scale, const float* __restrict__ k_scale,
                     __nv_bfloat16* __restrict__ qh, __nv_bfloat16* __restrict__ ql,
                     __nv_bfloat16* __restrict__ kh, __nv_bfloat16* __restrict__ kl) {
    int row = blockIdx.x;
    const bool is_q = row < Mrows * Nn;
    const int heads = is_q ? Nn : Kk;
    const int col0  = is_q ? 0 : 2048;
    const float post_scale = is_q ? SCALEf : 1.0f;
    const float* scale = is_q ? q_scale : k_scale;
    __nv_bfloat16* outhi = is_q ? qh : kh;
    __nv_bfloat16* outlo = is_q ? ql : kl;
    if (!is_q) row -= Mrows * Nn;

    const int h    = threadIdx.x;
    const int trow = row / heads;
    const int n    = row - trow * heads;
    const int b    = trow >> 11;
    const int t    = trow & 2047;

    float v = in[(size_t)trow * 4096 + col0 + n * Hh + h];
    float ss = v * v;
#pragma unroll
    for (int o = 16; o; o >>= 1) ss += __shfl_xor_sync(0xffffffffu, ss, o);
    __shared__ float warpsum[4];
    __shared__ float s_n[Hh];
    if ((h & 31) == 0) warpsum[h >> 5] = ss;
    __syncthreads();
    float total = warpsum[0] + warpsum[1] + warpsum[2] + warpsum[3];
    float inv_rms = rsqrtf(total * (1.0f / 128.0f) + EPSf);
    s_n[h] = v * inv_rms * scale[h];
    __syncthreads();

    float2 sc = g_rope[(size_t)trow * 64 + (h & 63)];
    float out = (h < 64) ? (s_n[h] * sc.y - s_n[h + 64] * sc.x)
                         : (s_n[h] * sc.y + s_n[h - 64] * sc.x);
    out *= post_scale;
    __nv_bfloat16 hi = __float2bfloat16(out);
    __nv_bfloat16 lo = __float2bfloat16(out - __bfloat162float(hi));
    size_t o = ((size_t)(b * heads + n) * Tt + t) * Hh + h;
    outhi[o] = hi;
    outlo[o] = lo;
}

// ---------------------------------------------------------------------------
// HMMA flash attention, GQA-paired (one CTA per kv-head, both q-heads).
// Longest-first q-tile order: blockIdx.x = 0 handles the LAST (largest) q tile.
// ---------------------------------------------------------------------------
#define AT_ST0  65536
#define AT_POS  196608
#define AT_SEG  204800
#define AT_META 212992
#define ATT_SMEM (212992 + 512)

__global__ __launch_bounds__(256)
void attn_hmma(const int* __restrict__ seg_g) {
    extern __shared__ char sm[];
    const uint32_t sb = smem_u32(sm);
    int* sPos  = (int*)(sm + AT_POS);
    int* sSeg  = (int*)(sm + AT_SEG);
    int* sKmin = (int*)(sm + AT_META);
    int* sTiles = sKmin + 32;
    int* sCtl   = sTiles + 32;

    const int tid = threadIdx.x, lane = tid & 31, warp = tid >> 5;
    const int qbase = (gridDim.x - 1 - blockIdx.x) * 64;   // longest-first
    const int kvh = blockIdx.y, b = blockIdx.z;
    const int hsel = warp >> 2;
    const int mwarp = warp & 3;
    const int n = kvh * 2 + hsel;

    for (int i = tid; i < 2048; i += 256) {
        sPos[i] = g_pos[b * Tt + i];
        sSeg[i] = seg_g[b * Tt + i];
    }
    for (int i = tid; i < 2048; i += 256) {
        int hh = i >> 10;
        int j = i & 1023;
        int r = j >> 4, u = j & 15;
        uint32_t off = hh * 32768 + ((u >> 3) << 13) + SW128(r * 128 + (u & 7) * 16);
        const char* qh = (const char*)(g_qhh + ((size_t)(b * Nn + kvh * 2 + hh) * Tt + qbase) * Hh);
        const char* ql = (const char*)(g_qhl + ((size_t)(b * Nn + kvh * 2 + hh) * Tt + qbase) * Hh);
        *(uint4*)(sm + off)         = *(const uint4*)(qh + r * 256 + u * 16);
        *(uint4*)(sm + 16384 + off) = *(const uint4*)(ql + r * 256 + u * 16);
    }
    __syncthreads();

    {
#pragma unroll
        for (int j = 0; j < 4; j++) {
            int tt = warp * 4 + j;
            int mn = min(sPos[tt * 64 + lane], sPos[tt * 64 + 32 + lane]);
#pragma unroll
            for (int o = 16; o; o >>= 1) mn = min(mn, __shfl_xor_sync(0xffffffffu, mn, o));
            if (lane == 0) sKmin[tt] = mn;
        }
        if (warp == 0) {
            int v = max(sPos[qbase + lane], sPos[qbase + 32 + lane]);
#pragma unroll
            for (int o = 16; o; o >>= 1) v = max(v, __shfl_xor_sync(0xffffffffu, v, o));
            if (lane == 0) sCtl[0] = v;
        }
    }
    __syncthreads();
    if (tid == 0) {
        int qmax = sCtl[0], na = 0;
        for (int tt = 0; tt < 32; tt++)
            if (sKmin[tt] <= qmax) sTiles[na++] = tt;
        sCtl[1] = na;
    }
    __syncthreads();
    const int nactive = sCtl[1];

    const char* kh = (const char*)(g_khh + ((size_t)(b * Kk + kvh) * Tt) * Hh);
    const char* kl = (const char*)(g_khl + ((size_t)(b * Kk + kvh) * Tt) * Hh);
    const char* vh = (const char*)(g_vhh + ((size_t)(b * Kk + kvh) * Tt) * Hh);
    const char* vl = (const char*)(g_vhl + ((size_t)(b * Kk + kvh) * Tt) * Hh);

#define AT_ISSUE(tt, st) do {                                                \
    const int sbase_ = (tt) * 64;                                            \
    uint32_t stb = sb + AT_ST0 + (st) * 65536;                               \
    for (int i = tid; i < 1024; i += 256) {                                  \
        int r = i >> 4, u = i & 15;                                          \
        uint32_t off = ((u >> 3) << 13) + SW128(r * 128 + (u & 7) * 16);     \
        size_t go = (size_t)(sbase_ + r) * 256 + u * 16;                     \
        CP_ASYNC16(stb + off,         kh + go);                              \
        CP_ASYNC16(stb + 16384 + off, kl + go);                              \
        CP_ASYNC16(stb + 32768 + off, vh + go);                              \
        CP_ASYNC16(stb + 49152 + off, vl + go);                              \
    }                                                                        \
} while (0)

    const int r_lo = mwarp * 16 + (lane >> 2);
    const int qp0 = sPos[qbase + r_lo];
    const int qp1 = sPos[qbase + r_lo + 8];
    const int qs0 = sSeg[qbase + r_lo];
    const int qs1 = sSeg[qbase + r_lo + 8];

    float d_o[16][4];
#pragma unroll
    for (int nt = 0; nt < 16; nt++)
#pragma unroll
        for (int j = 0; j < 4; j++) d_o[nt][j] = 0.f;
    float m0 = -1e30f, m1 = -1e30f, l0 = 0.f, l1 = 0.f;

    const int qrow_l = mwarp * 16 + (lane & 7) + ((lane >> 3) & 1) * 8;
    const int krow_l = ((lane >> 4) & 1) * 8 + (lane & 7);
    const int vrow_l = (((lane >> 3) & 1) << 3) + (lane & 7);
    const int qh_sel = (lane >> 4) << 3;
    const int kh_sel = ((lane >> 3) & 1) << 3;
    const int vh_sel = (lane >> 4) << 3;
    const uint32_t qpanel = sb + hsel * 32768;

    if (nactive > 0) { AT_ISSUE(sTiles[0], 0); CP_COMMIT(); }

    for (int j = 0; j < nactive; j++) {
        const int tt = sTiles[j];
        const int sbase = tt * 64;
        if (j + 1 < nactive) { AT_ISSUE(sTiles[j + 1], (j + 1) & 1); CP_COMMIT(); CP_WAIT(1); }
        else                 { CP_WAIT(0); }
        __syncthreads();

        const uint32_t stb = sb + AT_ST0 + (j & 1) * 65536;

        float ds[8][4];
#pragma unroll
        for (int nt = 0; nt < 8; nt++)
#pragma unroll
            for (int jj = 0; jj < 4; jj++) ds[nt][jj] = 0.f;

#pragma unroll
        for (int ks = 0; ks < 8; ks++) {
            int hq = ks * 16 + qh_sel;
            uint32_t qoff = ((hq >> 6) << 13) + SW128(qrow_l * 128 + ((hq & 63) << 1));
            uint32_t aH[4], aL[4];
            LDSM_X4(aH, qpanel + qoff);
            LDSM_X4(aL, qpanel + 16384 + qoff);
            int hk = ks * 16 + kh_sel;
            uint32_t kpan = ((hk >> 6) << 13);
            uint32_t kcol = (hk & 63) << 1;
#pragma unroll
            for (int np = 0; np < 4; np++) {
                uint32_t addr = stb + kpan + SW128((np * 16 + krow_l) * 128 + kcol);
                uint32_t tH[4], tL[4];
                LDSM_X4(tH, addr);
                LDSM_X4(tL, addr + 16384);
                MMA16816(ds[2*np],   aH, tH[0], tH[1]);
                MMA16816(ds[2*np],   aH, tL[0], tL[1]);
                MMA16816(ds[2*np],   aL, tH[0], tH[1]);
                MMA16816(ds[2*np+1], aH, tH[2], tH[3]);
                MMA16816(ds[2*np+1], aH, tL[2], tL[3]);
                MMA16816(ds[2*np+1], aL, tH[2], tH[3]);
            }
        }

#pragma unroll
        for (int nt = 0; nt < 8; nt++) {
            int c = sbase + nt * 8 + (lane & 3) * 2;
            int kp0 = sPos[c], kp1 = sPos[c + 1];
            int ks0 = sSeg[c], ks1 = sSeg[c + 1];
            if (!(kp0 <= qp0 && ks0 == qs0)) ds[nt][0] = -1e30f;
            if (!(kp1 <= qp0 && ks1 == qs0)) ds[nt][1] = -1e30f;
            if (!(kp0 <= qp1 && ks0 == qs1)) ds[nt][2] = -1e30f;
            if (!(kp1 <= qp1 && ks1 == qs1)) ds[nt][3] = -1e30f;
        }

        float tm0 = -1e30f, tm1 = -1e30f;
#pragma unroll
        for (int nt = 0; nt < 8; nt++) {
            tm0 = fmaxf(tm0, fmaxf(ds[nt][0], ds[nt][1]));
            tm1 = fmaxf(tm1, fmaxf(ds[nt][2], ds[nt][3]));
        }
        tm0 = fmaxf(tm0, __shfl_xor_sync(0xffffffffu, tm0, 1));
        tm0 = fmaxf(tm0, __shfl_xor_sync(0xffffffffu, tm0, 2));
        tm1 = fmaxf(tm1, __shfl_xor_sync(0xffffffffu, tm1, 1));
        tm1 = fmaxf(tm1, __shfl_xor_sync(0xffffffffu, tm1, 2));
        float nm0 = fmaxf(m0, tm0), nm1 = fmaxf(m1, tm1);
        float a0 = __expf(m0 - nm0), a1 = __expf(m1 - nm1);
        float gg0 = (nm0 > -0.9e30f) ? 1.f : 0.f;
        float gg1 = (nm1 > -0.9e30f) ? 1.f : 0.f;
        float s0 = 0.f, s1 = 0.f;
#pragma unroll
        for (int nt = 0; nt < 8; nt++) {
            ds[nt][0] = gg0 * __expf(ds[nt][0] - nm0);
            ds[nt][1] = gg0 * __expf(ds[nt][1] - nm0);
            ds[nt][2] = gg1 * __expf(ds[nt][2] - nm1);
            ds[nt][3] = gg1 * __expf(ds[nt][3] - nm1);
            s0 += ds[nt][0] + ds[nt][1];
            s1 += ds[nt][2] + ds[nt][3];
        }
        s0 += __shfl_xor_sync(0xffffffffu, s0, 1);
        s0 += __shfl_xor_sync(0xffffffffu, s0, 2);
        s1 += __shfl_xor_sync(0xffffffffu, s1, 1);
        s1 += __shfl_xor_sync(0xffffffffu, s1, 2);
        l0 = l0 * a0 + s0; m0 = nm0;
        l1 = l1 * a1 + s1; m1 = nm1;
#pragma unroll
        for (int nt = 0; nt < 16; nt++) {
            d_o[nt][0] *= a0; d_o[nt][1] *= a0;
            d_o[nt][2] *= a1; d_o[nt][3] *= a1;
        }

        uint32_t Ph[4][4], Pl[4][4];
#pragma unroll
        for (int kb = 0; kb < 4; kb++) {
            Ph[kb][0] = split2(ds[2*kb][0],   ds[2*kb][1],   Pl[kb][0]);
            Ph[kb][1] = split2(ds[2*kb][2],   ds[2*kb][3],   Pl[kb][1]);
            Ph[kb][2] = split2(ds[2*kb+1][0], ds[2*kb+1][1], Pl[kb][2]);
            Ph[kb][3] = split2(ds[2*kb+1][2], ds[2*kb+1][3], Pl[kb][3]);
        }

#pragma unroll
        for (int ntp = 0; ntp < 8; ntp++) {
            int hv = ntp * 16 + vh_sel;
            uint32_t vpan = ((hv >> 6) << 13);
            uint32_t vcol = (hv & 63) << 1;
#pragma unroll
            for (int kb = 0; kb < 4; kb++) {
                uint32_t addr = stb + 32768 + vpan + SW128((kb * 16 + vrow_l) * 128 + vcol);
                uint32_t tH[4], tL[4];
                LDSM_X4_T(tH, addr);
                LDSM_X4_T(tL, addr + 16384);
                MMA16816(d_o[2*ntp],   Ph[kb], tH[0], tH[1]);
                MMA16816(d_o[2*ntp],   Pl[kb], tH[0], tH[1]);
                MMA16816(d_o[2*ntp],   Ph[kb], tL[0], tL[1]);
                MMA16816(d_o[2*ntp+1], Ph[kb], tH[2], tH[3]);
                MMA16816(d_o[2*ntp+1], Pl[kb], tH[2], tH[3]);
                MMA16816(d_o[2*ntp+1], Ph[kb], tL[2], tL[3]);
            }
        }
        __syncthreads();
    }
#undef AT_ISSUE

    float il0 = (l0 > 0.f) ? (1.f / l0) : 0.f;
    float il1 = (l1 > 0.f) ? (1.f / l1) : 0.f;
    size_t base0 = ((size_t)(b * Tt + qbase + r_lo))     * 2048 + n * 128;
    size_t base1 = ((size_t)(b * Tt + qbase + r_lo + 8)) * 2048 + n * 128;
#pragma unroll
    for (int nt = 0; nt < 16; nt++) {
        int h = nt * 8 + (lane & 3) * 2;
        uint32_t lop;
        uint32_t hip = split2(d_o[nt][0] * il0, d_o[nt][1] * il0, lop);
        *(uint32_t*)(g_atthi + base0 + h) = hip;
        *(uint32_t*)(g_attlo + base0 + h) = lop;
        hip = split2(d_o[nt][2] * il1, d_o[nt][3] * il1, lop);
        *(uint32_t*)(g_atthi + base1 + h) = hip;
        *(uint32_t*)(g_attlo + base1 + h) = lop;
    }
}

// ---------------------------------------------------------------------------
extern "C" void kernel_launch(void* const* d_in, const int* in_sizes, int n_in,
                              void* d_out, int out_size) {
    const float* x       = (const float*)d_in[0];
    const int*   seg     = (const int*)  d_in[1];
    const float* wq      = (const float*)d_in[2];
    const float* wk      = (const float*)d_in[3];
    const float* wv      = (const float*)d_in[4];
    const float* wo      = (const float*)d_in[5];
    const float* q_scale = (const float*)d_in[6];
    const float* k_scale = (const float*)d_in[7];
    float* out = (float*)d_out;

    float* qkv;
    cudaGetSymbolAddress((void**)&qkv, g_qkv);
    __nv_bfloat16 *xhi, *xlo, *ahi, *alo;
    __nv_bfloat16 *wch, *wcl, *woh, *wol;
    __nv_bfloat16 *qhh, *qhl, *khh, *khl, *vhh, *vhl;
    cudaGetSymbolAddress((void**)&xhi, g_xhi);
    cudaGetSymbolAddress((void**)&xlo, g_xlo);
    cudaGetSymbolAddress((void**)&ahi, g_atthi);
    cudaGetSymbolAddress((void**)&alo, g_attlo);
    cudaGetSymbolAddress((void**)&wch, g_wqkvT_hi);
    cudaGetSymbolAddress((void**)&wcl, g_wqkvT_lo);
    cudaGetSymbolAddress((void**)&woh, g_woT_hi);
    cudaGetSymbolAddress((void**)&wol, g_woT_lo);
    cudaGetSymbolAddress((void**)&qhh, g_qhh);
    cudaGetSymbolAddress((void**)&qhl, g_qhl);
    cudaGetSymbolAddress((void**)&khh, g_khh);
    cudaGetSymbolAddress((void**)&khl, g_khl);
    cudaGetSymbolAddress((void**)&vhh, g_vhh);
    cudaGetSymbolAddress((void**)&vhl, g_vhl);

    cudaFuncSetAttribute(gemm_hmma, cudaFuncAttributeMaxDynamicSharedMemorySize,
                         GEMM_SMEM);
    cudaFuncSetAttribute(attn_hmma, cudaFuncAttributeMaxDynamicSharedMemorySize,
                         ATT_SMEM);

    pos_kernel<<<Bb, 256>>>(seg);
    rope_kernel<<<Mrows * 64 / 256, 256>>>();

    // split conversions (wq/wk/wv into one concatenated transposed buffer)
    conv_split<<<1024, 256>>>(x, xhi, xlo, (size_t)Mrows * Dd / 4);
    conv_tsplit<<<dim3(2048 / 32, 1024 / 32), dim3(32, 8)>>>(
        wq, wch, wcl, 1024, 2048);
    conv_tsplit<<<dim3(1024 / 32, 1024 / 32), dim3(32, 8)>>>(
        wk, wch + (size_t)2048 * 1024, wcl + (size_t)2048 * 1024, 1024, 1024);
    conv_tsplit<<<dim3(1024 / 32, 1024 / 32), dim3(32, 8)>>>(
        wv, wch + (size_t)3072 * 1024, wcl + (size_t)3072 * 1024, 1024, 1024);
    conv_tsplit<<<dim3(1024 / 32, 2048 / 32), dim3(32, 8)>>>(wo, woh, wol, 2048, 1024);

    // Combined QKV projection: q|k fp32 -> g_qkv, v -> split head-major
    gemm_hmma<<<dim3(32, Mrows / 256), 256, GEMM_SMEM>>>(
        xhi, xlo, wch, wcl, qkv, vhh, vhl, 3, 4096, 1024);

    // RMSNorm + RoPE(table) + split (q and k in one launch)
    norm_rope_split<<<Mrows * (Nn + Kk), 128>>>(
        qkv, q_scale, k_scale, qhh, qhl, khh, khl);

    // HMMA flash attention (GQA-paired, cp.async pipelined, longest-first)
    attn_hmma<<<dim3(Tt / 64, Kk, Bb), 256, ATT_SMEM>>>(seg);

    // output projection (fp32 store to d_out) — 128 CTAs = single wave
    gemm_hmma<<<dim3(1024 / 128, Mrows / 256), 256, GEMM_SMEM>>>(
        ahi, alo, woh, wol, out, (__nv_bfloat16*)0, (__nv_bfloat16*)0, 0, 1024, 2048);
}